// round 2
// baseline (speedup 1.0000x reference)
#include <cuda_runtime.h>
#include <math.h>

#define BB   16
#define SL   2048
#define DD   128
#define HH   4
#define NLAY 4
#define DKH  32
#define DFF  256
#define NF   129
#define DMG  16
#define INTD 11
#define NTOK (BB*SL)
#define FMIN_F (-3.402823466e38f)

// ---------------- scratch (device globals: allocation-free) ----------------
__device__ float g_x[NTOK*DD];        // activations [tok][128]
__device__ float g_qkv[NTOK*3*DD];    // [tok][384]: q(h*32+e) | k | v
__device__ float g_o[NTOK*DD];        // attention out [tok][h*32+e]
__device__ float g_ff[NTOK*DFF];      // FFN hidden
__device__ float g_w[DD*3*DD];        // repacked QKV weights [d][384]
__device__ float g_demo[BB*DD];
__device__ float g_att[BB*SL];
__device__ float g_ts[BB*DD];
__device__ unsigned char g_mask[NTOK];
__device__ int g_cnt[2];              // [0]!=0 -> not int32 ; [1]!=0 -> not float32

// ---------------- mask dtype detection + normalization ----------------------
__global__ void mask_reset_kernel() {
    if (threadIdx.x < 2) g_cnt[threadIdx.x] = 0;
}
// scan first NTOK/4 words (32KB) — safe under int32/float32/uint8 hypotheses
__global__ void mask_scan_kernel(const unsigned int* __restrict__ w) {
    int i = blockIdx.x*256 + threadIdx.x;   // < NTOK/4 = 8192
    unsigned int v = w[i];
    if (v > 1u) atomicOr(&g_cnt[0], 1);
    if (v != 0u && v != 0x3F800000u) atomicOr(&g_cnt[1], 1);
}
__global__ void mask_convert_kernel(const void* __restrict__ p) {
    int i = blockIdx.x*256 + threadIdx.x;   // < NTOK
    unsigned char m;
    if (g_cnt[0] == 0)       m = (unsigned char)(((const int*)p)[i] != 0);
    else if (g_cnt[1] == 0)  m = (unsigned char)(((const float*)p)[i] != 0.0f);
    else                     m = (unsigned char)(((const unsigned char*)p)[i] != 0);
    g_mask[i] = m;
}

// ---------------- embedding: x = CVE(t) + CVE(v) + var_table[var] ----------
__global__ void embed_kernel(const float* __restrict__ values, const float* __restrict__ times,
                             const int* __restrict__ vars,
                             const float* __restrict__ W1t, const float* __restrict__ b1t,
                             const float* __restrict__ W2t,
                             const float* __restrict__ W1v, const float* __restrict__ b1v,
                             const float* __restrict__ W2v,
                             const float* __restrict__ vtab)
{
    int tok = blockIdx.x;
    int d   = threadIdx.x;                 // 0..127
    __shared__ float tt[INTD], vv[INTD];
    if (d < INTD) {
        float t = times[tok], v = values[tok];
        tt[d] = tanhf(t * W1t[d] + b1t[d]);
        vv[d] = tanhf(v * W1v[d] + b1v[d]);
    }
    __syncthreads();
    int var = vars[tok];
    float acc = vtab[var*DD + d];
#pragma unroll
    for (int i = 0; i < INTD; i++)
        acc += tt[i]*W2t[i*DD+d] + vv[i]*W2v[i*DD+d];
    g_x[(size_t)tok*DD + d] = acc;
}

// ---------------- repack Wq/Wk/Wv (layer i) into [d][384] -------------------
__global__ void repack_kernel(const float* __restrict__ Wq, const float* __restrict__ Wk,
                              const float* __restrict__ Wv)
{
    int idx = blockIdx.x*blockDim.x + threadIdx.x;   // < 3*4096*4 = 49152
    int sel = idx >> 14;
    int r   = idx & 16383;                            // h*4096 + d*32 + e
    int h   = r >> 12;
    int d   = (r >> 5) & 127;
    int e   = r & 31;
    const float* src = sel == 0 ? Wq : (sel == 1 ? Wk : Wv);
    g_w[d*384 + sel*128 + h*32 + e] = src[r];
}

// ---------------- generic SGEMM 128x128x8, M=32768 --------------------------
// epi: 0 none | 1 +=C | 2 bias+gelu | 3 bias+ +=C
__global__ __launch_bounds__(256)
void sgemm_kernel(const float* __restrict__ A, const float* __restrict__ W,
                  const float* __restrict__ bias, float* __restrict__ C,
                  int N, int K, int epi)
{
    const int BK = 8;
    __shared__ float As[BK][128];
    __shared__ float Bs[BK][128];
    int bn = blockIdx.x * 128;
    int bm = blockIdx.y * 128;
    int tid = threadIdx.x;
    int tx = tid & 15, ty = tid >> 4;
    float acc[8][8];
#pragma unroll
    for (int i = 0; i < 8; i++)
#pragma unroll
        for (int j = 0; j < 8; j++) acc[i][j] = 0.f;

    int arow = tid >> 1, acol = (tid & 1) * 4;
    int brow = tid >> 5, bcol = (tid & 31) * 4;
    const float* Ap = A + (size_t)(bm + arow)*K + acol;
    const float* Wp = W + (size_t)brow*N + bn + bcol;

    for (int k0 = 0; k0 < K; k0 += BK) {
        float4 a4 = *(const float4*)(Ap + k0);
        As[acol+0][arow] = a4.x; As[acol+1][arow] = a4.y;
        As[acol+2][arow] = a4.z; As[acol+3][arow] = a4.w;
        *(float4*)&Bs[brow][bcol] = *(const float4*)(Wp + (size_t)k0*N);
        __syncthreads();
#pragma unroll
        for (int kk = 0; kk < BK; kk++) {
            float4 a0 = *(const float4*)&As[kk][ty*8];
            float4 a1 = *(const float4*)&As[kk][ty*8+4];
            float4 b0 = *(const float4*)&Bs[kk][tx*8];
            float4 b1 = *(const float4*)&Bs[kk][tx*8+4];
            float ar[8] = {a0.x,a0.y,a0.z,a0.w,a1.x,a1.y,a1.z,a1.w};
            float br[8] = {b0.x,b0.y,b0.z,b0.w,b1.x,b1.y,b1.z,b1.w};
#pragma unroll
            for (int i = 0; i < 8; i++)
#pragma unroll
                for (int j = 0; j < 8; j++)
                    acc[i][j] += ar[i]*br[j];
        }
        __syncthreads();
    }
#pragma unroll
    for (int i = 0; i < 8; i++) {
        int row = bm + ty*8 + i;
        float* Crow = C + (size_t)row*N + bn + tx*8;
#pragma unroll
        for (int j = 0; j < 8; j++) {
            float v = acc[i][j];
            if (epi >= 2) v += bias[bn + tx*8 + j];
            if (epi == 2) v = 0.5f*v*(1.f + erff(v*0.7071067811865476f));
            if (epi == 1 || epi == 3) v += Crow[j];
            Crow[j] = v;
        }
    }
}

// ---------------- flash attention (fp32, exact FMIN mask semantics) ---------
__global__ __launch_bounds__(128)
void flash_kernel()
{
    const int KB = 64;
    int bh = blockIdx.y;
    int b = bh >> 2, h = bh & 3;
    int q = blockIdx.x*128 + threadIdx.x;
    __shared__ float Ks[KB][DKH];
    __shared__ float Vs[KB][DKH];
    __shared__ unsigned char ms[KB];

    float qv[DKH];
    const float* qptr = g_qkv + (size_t)(b*SL + q)*384 + h*32;
#pragma unroll
    for (int e = 0; e < DKH; e += 4) {
        float4 f = *(const float4*)(qptr + e);
        qv[e] = f.x; qv[e+1] = f.y; qv[e+2] = f.z; qv[e+3] = f.w;
    }
    bool mq = g_mask[b*SL + q] != 0;
    float mx = -INFINITY, lsum = 0.f;
    float acc[DKH];
#pragma unroll
    for (int e = 0; e < DKH; e++) acc[e] = 0.f;

    int tid = threadIdx.x;
    for (int k0 = 0; k0 < SL; k0 += KB) {
#pragma unroll
        for (int it = 0; it < 4; it++) {
            int v = tid + it*128;              // 0..511 float4s
            int row = v >> 3, c4 = (v & 7) * 4;
            const float* base = g_qkv + (size_t)(b*SL + k0 + row)*384 + h*32;
            *(float4*)&Ks[row][c4] = *(const float4*)(base + 128 + c4);
            *(float4*)&Vs[row][c4] = *(const float4*)(base + 256 + c4);
        }
        if (tid < KB) ms[tid] = g_mask[b*SL + k0 + tid];
        __syncthreads();

#pragma unroll 4
        for (int j = 0; j < KB; j++) {
            float d0=0.f, d1=0.f, d2=0.f, d3=0.f;
#pragma unroll
            for (int e = 0; e < DKH; e += 4) {
                d0 += qv[e]  *Ks[j][e];
                d1 += qv[e+1]*Ks[j][e+1];
                d2 += qv[e+2]*Ks[j][e+2];
                d3 += qv[e+3]*Ks[j][e+3];
            }
            bool pm = mq && (ms[j] != 0);
            float s = pm ? ((d0+d1)+(d2+d3)) : FMIN_F;
            if (s > mx) {
                float c = __expf(mx - s);
                lsum *= c;
#pragma unroll
                for (int e = 0; e < DKH; e++) acc[e] *= c;
                mx = s;
            }
            float p = __expf(s - mx);
            lsum += p;
#pragma unroll
            for (int e = 0; e < DKH; e++) acc[e] += p*Vs[j][e];
        }
        __syncthreads();
    }
    float inv = 1.f / lsum;
    float* optr = g_o + (size_t)(b*SL + q)*DD + h*32;
#pragma unroll
    for (int e = 0; e < DKH; e++) optr[e] = acc[e]*inv;
}

// ---------------- fusion attention logits -----------------------------------
__global__ void fuse_att_kernel(const float* __restrict__ Wf, const float* __restrict__ bf,
                                const float* __restrict__ uf)
{
    int tok = blockIdx.x;
    int d = threadIdx.x;
    __shared__ float xs[DD];
    __shared__ float red[128];
    xs[d] = g_x[(size_t)tok*DD + d];
    __syncthreads();
    float acc = bf[d];
#pragma unroll 8
    for (int k = 0; k < DD; k++) acc += xs[k]*Wf[k*DD + d];
    red[d] = tanhf(acc)*uf[d];
    __syncthreads();
    for (int s = 64; s > 0; s >>= 1) {
        if (d < s) red[d] += red[d + s];
        __syncthreads();
    }
    if (d == 0) g_att[tok] = g_mask[tok] ? red[0] : FMIN_F;
}

// ---------------- masked softmax pooling ------------------------------------
__global__ void pool_kernel()
{
    int b = blockIdx.x;
    int tid = threadIdx.x;                 // 256
    __shared__ float w[SL];
    __shared__ float red[256];
    float mx = -INFINITY;
    for (int l = tid; l < SL; l += 256) mx = fmaxf(mx, g_att[b*SL + l]);
    red[tid] = mx; __syncthreads();
    for (int s = 128; s > 0; s >>= 1) { if (tid < s) red[tid] = fmaxf(red[tid], red[tid+s]); __syncthreads(); }
    mx = red[0]; __syncthreads();
    float sum = 0.f;
    for (int l = tid; l < SL; l += 256) { float e = __expf(g_att[b*SL+l] - mx); w[l] = e; sum += e; }
    red[tid] = sum; __syncthreads();
    for (int s = 128; s > 0; s >>= 1) { if (tid < s) red[tid] += red[tid+s]; __syncthreads(); }
    float inv = 1.f / red[0];
    __syncthreads();
    int d = tid & 127, half = tid >> 7;
    float acc = 0.f;
    for (int l = half*1024; l < half*1024 + 1024; l++)
        acc += w[l]*g_x[((size_t)b*SL + l)*DD + d];
    red[tid] = acc; __syncthreads();
    if (tid < 128) g_ts[b*DD + tid] = (red[tid] + red[tid+128])*inv;
}

// ---------------- demographics MLP -------------------------------------------
__global__ void demo_kernel(const float* __restrict__ demo, const float* __restrict__ Wd1,
                            const float* __restrict__ bd1, const float* __restrict__ Wd2,
                            const float* __restrict__ bd2)
{
    int b = blockIdx.x;
    int tid = threadIdx.x;                  // 256
    __shared__ float ds[DMG];
    __shared__ float hs[256];
    if (tid < DMG) ds[tid] = demo[b*DMG + tid];
    __syncthreads();
    float a = bd1[tid];
#pragma unroll
    for (int k = 0; k < DMG; k++) a += ds[k]*Wd1[k*256 + tid];
    hs[tid] = tanhf(a);
    __syncthreads();
    if (tid < DD) {
        float a2 = bd2[tid];
#pragma unroll 8
        for (int k = 0; k < 256; k++) a2 += hs[k]*Wd2[k*DD + tid];
        g_demo[b*DD + tid] = a2;
    }
}

// ---------------- head --------------------------------------------------------
__global__ void head_kernel(const float* __restrict__ Wh, const float* __restrict__ bh,
                            float* __restrict__ out)
{
    int b = blockIdx.x;
    int tid = threadIdx.x;                 // 256
    __shared__ float es[256];
    es[tid] = (tid < 128) ? g_ts[b*DD + tid] : g_demo[b*DD + (tid - 128)];
    __syncthreads();
    if (tid < NF) {
        float acc = bh[tid];
#pragma unroll 8
        for (int k = 0; k < 256; k++) acc += es[k]*Wh[k*NF + tid];
        out[b*NF + tid] = acc;
    }
}

// ---------------- orchestration ------------------------------------------------
extern "C" void kernel_launch(void* const* d_in, const int* in_sizes, int n_in,
                              void* d_out, int out_size)
{
    const float* values = (const float*)d_in[0];
    const float* times  = (const float*)d_in[1];
    const int*   vars   = (const int*)d_in[2];
    const void*  maskraw = d_in[3];
    const float* demo   = (const float*)d_in[4];
    const float* W1t = (const float*)d_in[5];
    const float* b1t = (const float*)d_in[6];
    const float* W2t = (const float*)d_in[7];
    const float* W1v = (const float*)d_in[8];
    const float* b1v = (const float*)d_in[9];
    const float* W2v = (const float*)d_in[10];
    const float* vtab = (const float*)d_in[11];
    const float* Wq = (const float*)d_in[12];
    const float* Wk = (const float*)d_in[13];
    const float* Wv = (const float*)d_in[14];
    const float* Wo = (const float*)d_in[15];
    const float* W1 = (const float*)d_in[16];
    const float* b1 = (const float*)d_in[17];
    const float* W2 = (const float*)d_in[18];
    const float* b2 = (const float*)d_in[19];
    const float* Wf = (const float*)d_in[20];
    const float* bf = (const float*)d_in[21];
    const float* uf = (const float*)d_in[22];
    const float* Wd1 = (const float*)d_in[23];
    const float* bd1 = (const float*)d_in[24];
    const float* Wd2 = (const float*)d_in[25];
    const float* bd2 = (const float*)d_in[26];
    const float* Wh = (const float*)d_in[27];
    const float* bh = (const float*)d_in[28];
    float* out = (float*)d_out;

    float *xp, *qkvp, *op, *ffp, *wp;
    cudaGetSymbolAddress((void**)&xp,   g_x);
    cudaGetSymbolAddress((void**)&qkvp, g_qkv);
    cudaGetSymbolAddress((void**)&op,   g_o);
    cudaGetSymbolAddress((void**)&ffp,  g_ff);
    cudaGetSymbolAddress((void**)&wp,   g_w);

    // normalize mask dtype (int32 / float32 / uint8) into g_mask bytes
    mask_reset_kernel<<<1, 32>>>();
    mask_scan_kernel<<<NTOK/4/256, 256>>>((const unsigned int*)maskraw);
    mask_convert_kernel<<<NTOK/256, 256>>>(maskraw);

    demo_kernel<<<BB, 256>>>(demo, Wd1, bd1, Wd2, bd2);
    embed_kernel<<<NTOK, 128>>>(values, times, vars, W1t, b1t, W2t, W1v, b1v, W2v, vtab);

    for (int i = 0; i < NLAY; i++) {
        repack_kernel<<<192, 256>>>(Wq + i*HH*DD*DKH, Wk + i*HH*DD*DKH, Wv + i*HH*DD*DKH);
        sgemm_kernel<<<dim3(3, NTOK/128), 256>>>(xp, wp, nullptr, qkvp, 384, 128, 0);
        flash_kernel<<<dim3(SL/128, BB*HH), 128>>>();
        sgemm_kernel<<<dim3(1, NTOK/128), 256>>>(op, Wo + i*DD*DD, nullptr, xp, 128, 128, 1);
        sgemm_kernel<<<dim3(2, NTOK/128), 256>>>(xp, W1 + i*DD*DFF, b1 + i*DFF, ffp, 256, 128, 2);
        sgemm_kernel<<<dim3(1, NTOK/128), 256>>>(ffp, W2 + i*DFF*DD, b2 + i*DD, xp, 128, 256, 3);
    }

    fuse_att_kernel<<<NTOK, 128>>>(Wf, bf, uf);
    pool_kernel<<<BB, 256>>>();
    head_kernel<<<BB, 256>>>(Wh, bh, out);
}

// round 3
// speedup vs baseline: 2.2037x; 2.2037x over previous
#include <cuda_runtime.h>
#include <math.h>

#define BB   16
#define SL   2048
#define DD   128
#define HH   4
#define NLAY 4
#define DKH  32
#define DFF  256
#define NF   129
#define DMG  16
#define INTD 11
#define NTOK (BB*SL)
#define FMIN_F (-3.402823466e38f)

// ---------------- scratch (device globals: allocation-free) ----------------
__device__ float g_x[NTOK*DD];        // compacted activations [b*SL+j][128]
__device__ float g_qkv[NTOK*3*DD];    // [b*SL+j][384]: q | k | v (h*32+e)
__device__ float g_o[NTOK*DD];        // attention out
__device__ float g_ff[NTOK*DFF];      // FFN hidden
__device__ float g_w[DD*3*DD];        // repacked QKV weights [d][384]
__device__ float g_demo[BB*DD];
__device__ float g_att[BB*SL];
__device__ float g_ts[BB*DD];
__device__ unsigned char g_mask[NTOK];
__device__ int g_idx[NTOK];           // compacted j -> original l (per batch)
__device__ int g_nb[BB];              // valid count per batch
__device__ int g_npad[BB];            // round-up-128 of count
__device__ int g_cnt[2];              // dtype probes

// ---------------- mask dtype detection + normalization ----------------------
__global__ void mask_reset_kernel() {
    if (threadIdx.x < 2) g_cnt[threadIdx.x] = 0;
}
__global__ void mask_scan_kernel(const unsigned int* __restrict__ w) {
    int i = blockIdx.x*256 + threadIdx.x;   // < NTOK/4 = 8192 words (32KB, safe)
    unsigned int v = w[i];
    if (v > 1u) atomicOr(&g_cnt[0], 1);
    if (v != 0u && v != 0x3F800000u) atomicOr(&g_cnt[1], 1);
}
__global__ void mask_convert_kernel(const void* __restrict__ p) {
    int i = blockIdx.x*256 + threadIdx.x;   // < NTOK
    unsigned char m;
    if (g_cnt[0] == 0)       m = (unsigned char)(((const int*)p)[i] != 0);
    else if (g_cnt[1] == 0)  m = (unsigned char)(((const float*)p)[i] != 0.0f);
    else                     m = (unsigned char)(((const unsigned char*)p)[i] != 0);
    g_mask[i] = m;
}

// ---------------- stable compaction: per-batch prefix sum -------------------
__global__ void compact_kernel()
{
    int b = blockIdx.x, tid = threadIdx.x;        // 256 threads
    __shared__ int sc[256];
    __shared__ int sbase;
    if (tid == 0) sbase = 0;
    __syncthreads();
    for (int c = 0; c < SL; c += 256) {
        int l = c + tid;
        int m = g_mask[b*SL + l];
        sc[tid] = m;
        __syncthreads();
#pragma unroll
        for (int s = 1; s < 256; s <<= 1) {
            int v = (tid >= s) ? sc[tid - s] : 0;
            __syncthreads();
            sc[tid] += v;
            __syncthreads();
        }
        int pos = sbase + sc[tid] - m;            // exclusive scan + base
        if (m) g_idx[b*SL + pos] = l;
        int tot = sc[255];
        __syncthreads();
        if (tid == 0) sbase += tot;
        __syncthreads();
    }
    if (tid == 0) { g_nb[b] = sbase; g_npad[b] = (sbase + 127) & ~127; }
}

// ---------------- embedding (compacted): x = CVE(t)+CVE(v)+var_table --------
__global__ void embed_kernel(const float* __restrict__ values, const float* __restrict__ times,
                             const int* __restrict__ vars,
                             const float* __restrict__ W1t, const float* __restrict__ b1t,
                             const float* __restrict__ W2t,
                             const float* __restrict__ W1v, const float* __restrict__ b1v,
                             const float* __restrict__ W2v,
                             const float* __restrict__ vtab)
{
    int tok = blockIdx.x;
    int b = tok >> 11, j = tok & 2047;
    int d = threadIdx.x;                 // 0..127
    if (j >= g_npad[b]) return;
    if (j >= g_nb[b]) { g_x[(size_t)tok*DD + d] = 0.f; return; }
    int l = g_idx[tok];
    __shared__ float tt[INTD], vv[INTD];
    if (d < INTD) {
        float t = times[b*SL + l], v = values[b*SL + l];
        tt[d] = tanhf(t * W1t[d] + b1t[d]);
        vv[d] = tanhf(v * W1v[d] + b1v[d]);
    }
    __syncthreads();
    int var = vars[b*SL + l];
    float acc = vtab[var*DD + d];
#pragma unroll
    for (int i = 0; i < INTD; i++)
        acc += tt[i]*W2t[i*DD+d] + vv[i]*W2v[i*DD+d];
    g_x[(size_t)tok*DD + d] = acc;
}

// ---------------- repack Wq/Wk/Wv (layer i) into [d][384] -------------------
__global__ void repack_kernel(const float* __restrict__ Wq, const float* __restrict__ Wk,
                              const float* __restrict__ Wv)
{
    int idx = blockIdx.x*blockDim.x + threadIdx.x;   // < 49152
    int sel = idx >> 14;
    int r   = idx & 16383;                            // h*4096 + d*32 + e
    int h   = r >> 12;
    int d   = (r >> 5) & 127;
    int e   = r & 31;
    const float* src = sel == 0 ? Wq : (sel == 1 ? Wk : Wv);
    g_w[d*384 + sel*128 + h*32 + e] = src[r];
}

// ---------------- SGEMM 128x128x8 over compacted rows ------------------------
// epi: 0 none | 1 +=C | 2 bias+gelu | 3 bias+ +=C
__global__ __launch_bounds__(256)
void sgemm_kernel(const float* __restrict__ A, const float* __restrict__ W,
                  const float* __restrict__ bias, float* __restrict__ C,
                  int N, int K, int epi)
{
    const int BK = 8;
    int bm = blockIdx.y * 128;
    if ((bm & 2047) >= g_npad[bm >> 11]) return;     // skip empty padded region
    __shared__ float As[BK][128];
    __shared__ float Bs[BK][128];
    int bn = blockIdx.x * 128;
    int tid = threadIdx.x;
    int tx = tid & 15, ty = tid >> 4;
    float acc[8][8];
#pragma unroll
    for (int i = 0; i < 8; i++)
#pragma unroll
        for (int j = 0; j < 8; j++) acc[i][j] = 0.f;

    int arow = tid >> 1, acol = (tid & 1) * 4;
    int brow = tid >> 5, bcol = (tid & 31) * 4;
    const float* Ap = A + (size_t)(bm + arow)*K + acol;
    const float* Wp = W + (size_t)brow*N + bn + bcol;

    for (int k0 = 0; k0 < K; k0 += BK) {
        float4 a4 = *(const float4*)(Ap + k0);
        As[acol+0][arow] = a4.x; As[acol+1][arow] = a4.y;
        As[acol+2][arow] = a4.z; As[acol+3][arow] = a4.w;
        *(float4*)&Bs[brow][bcol] = *(const float4*)(Wp + (size_t)k0*N);
        __syncthreads();
#pragma unroll
        for (int kk = 0; kk < BK; kk++) {
            float4 a0 = *(const float4*)&As[kk][ty*8];
            float4 a1 = *(const float4*)&As[kk][ty*8+4];
            float4 b0 = *(const float4*)&Bs[kk][tx*8];
            float4 b1 = *(const float4*)&Bs[kk][tx*8+4];
            float ar[8] = {a0.x,a0.y,a0.z,a0.w,a1.x,a1.y,a1.z,a1.w};
            float br[8] = {b0.x,b0.y,b0.z,b0.w,b1.x,b1.y,b1.z,b1.w};
#pragma unroll
            for (int i = 0; i < 8; i++)
#pragma unroll
                for (int j = 0; j < 8; j++)
                    acc[i][j] += ar[i]*br[j];
        }
        __syncthreads();
    }
#pragma unroll
    for (int i = 0; i < 8; i++) {
        int row = bm + ty*8 + i;
        float* Crow = C + (size_t)row*N + bn + tx*8;
#pragma unroll
        for (int j = 0; j < 8; j++) {
            float v = acc[i][j];
            if (epi >= 2) v += bias[bn + tx*8 + j];
            if (epi == 2) v = 0.5f*v*(1.f + erff(v*0.7071067811865476f));
            if (epi == 1 || epi == 3) v += Crow[j];
            Crow[j] = v;
        }
    }
}

// ---------------- flash attention over compacted tokens ---------------------
__global__ __launch_bounds__(128)
void flash_kernel()
{
    const int KB = 64;
    int bh = blockIdx.y;
    int b = bh >> 2, h = bh & 3;
    int n = g_nb[b];
    if ((int)(blockIdx.x*128) >= n) return;          // rows >= n_pad never touched
    int j = blockIdx.x*128 + threadIdx.x;            // compacted query index
    __shared__ float Ks[KB][DKH];
    __shared__ float Vs[KB][DKH];

    float qv[DKH];
    const float* qptr = g_qkv + (size_t)(b*SL + j)*384 + h*32;
#pragma unroll
    for (int e = 0; e < DKH; e += 4) {
        float4 f = *(const float4*)(qptr + e);
        qv[e] = f.x; qv[e+1] = f.y; qv[e+2] = f.z; qv[e+3] = f.w;
    }
    float mx = -INFINITY, lsum = 0.f;
    float acc[DKH];
#pragma unroll
    for (int e = 0; e < DKH; e++) acc[e] = 0.f;

    int tid = threadIdx.x;
    for (int k0 = 0; k0 < n; k0 += KB) {
        // rows k0..k0+63 < round64(n) <= n_pad : always finite (zero-padded)
#pragma unroll
        for (int it = 0; it < 4; it++) {
            int v = tid + it*128;              // 512 float4s
            int row = v >> 3, c4 = (v & 7) * 4;
            const float* base = g_qkv + (size_t)(b*SL + k0 + row)*384 + h*32;
            *(float4*)&Ks[row][c4] = *(const float4*)(base + 128 + c4);
            *(float4*)&Vs[row][c4] = *(const float4*)(base + 256 + c4);
        }
        __syncthreads();

#pragma unroll 4
        for (int jj = 0; jj < KB; jj++) {
            float d0=0.f, d1=0.f, d2=0.f, d3=0.f;
#pragma unroll
            for (int e = 0; e < DKH; e += 4) {
                d0 += qv[e]  *Ks[jj][e];
                d1 += qv[e+1]*Ks[jj][e+1];
                d2 += qv[e+2]*Ks[jj][e+2];
                d3 += qv[e+3]*Ks[jj][e+3];
            }
            float s = (k0 + jj < n) ? ((d0+d1)+(d2+d3)) : FMIN_F;
            if (s > mx) {
                float c = __expf(mx - s);
                lsum *= c;
#pragma unroll
                for (int e = 0; e < DKH; e++) acc[e] *= c;
                mx = s;
            }
            float p = __expf(s - mx);
            lsum += p;
#pragma unroll
            for (int e = 0; e < DKH; e++) acc[e] += p*Vs[jj][e];
        }
        __syncthreads();
    }
    float inv = 1.f / lsum;
    float* optr = g_o + (size_t)(b*SL + j)*DD + h*32;
#pragma unroll
    for (int e = 0; e < DKH; e++) optr[e] = acc[e]*inv;
}

// ---------------- fusion attention logits (compacted, all valid) ------------
__global__ void fuse_att_kernel(const float* __restrict__ Wf, const float* __restrict__ bf,
                                const float* __restrict__ uf)
{
    int tok = blockIdx.x;
    int b = tok >> 11, j = tok & 2047;
    if (j >= g_nb[b]) return;
    int d = threadIdx.x;
    __shared__ float xs[DD];
    __shared__ float red[128];
    xs[d] = g_x[(size_t)tok*DD + d];
    __syncthreads();
    float acc = bf[d];
#pragma unroll 8
    for (int k = 0; k < DD; k++) acc += xs[k]*Wf[k*DD + d];
    red[d] = tanhf(acc)*uf[d];
    __syncthreads();
    for (int s = 64; s > 0; s >>= 1) {
        if (d < s) red[d] += red[d + s];
        __syncthreads();
    }
    if (d == 0) g_att[tok] = red[0];
}

// ---------------- masked softmax pooling (compacted) ------------------------
__global__ void pool_kernel()
{
    int b = blockIdx.x;
    int n = g_nb[b];
    int tid = threadIdx.x;                 // 256
    __shared__ float w[SL];
    __shared__ float red[256];
    float mx = -INFINITY;
    for (int l = tid; l < n; l += 256) mx = fmaxf(mx, g_att[b*SL + l]);
    red[tid] = mx; __syncthreads();
    for (int s = 128; s > 0; s >>= 1) { if (tid < s) red[tid] = fmaxf(red[tid], red[tid+s]); __syncthreads(); }
    mx = red[0]; __syncthreads();
    float sum = 0.f;
    for (int l = tid; l < n; l += 256) { float e = __expf(g_att[b*SL+l] - mx); w[l] = e; sum += e; }
    red[tid] = sum; __syncthreads();
    for (int s = 128; s > 0; s >>= 1) { if (tid < s) red[tid] += red[tid+s]; __syncthreads(); }
    float inv = 1.f / red[0];
    __syncthreads();
    int d = tid & 127, half = tid >> 7;
    float acc = 0.f;
    for (int l = half; l < n; l += 2)
        acc += w[l]*g_x[((size_t)b*SL + l)*DD + d];
    red[tid] = acc; __syncthreads();
    if (tid < 128) g_ts[b*DD + tid] = (red[tid] + red[tid+128])*inv;
}

// ---------------- demographics MLP ------------------------------------------
__global__ void demo_kernel(const float* __restrict__ demo, const float* __restrict__ Wd1,
                            const float* __restrict__ bd1, const float* __restrict__ Wd2,
                            const float* __restrict__ bd2)
{
    int b = blockIdx.x;
    int tid = threadIdx.x;                  // 256
    __shared__ float ds[DMG];
    __shared__ float hs[256];
    if (tid < DMG) ds[tid] = demo[b*DMG + tid];
    __syncthreads();
    float a = bd1[tid];
#pragma unroll
    for (int k = 0; k < DMG; k++) a += ds[k]*Wd1[k*256 + tid];
    hs[tid] = tanhf(a);
    __syncthreads();
    if (tid < DD) {
        float a2 = bd2[tid];
#pragma unroll 8
        for (int k = 0; k < 256; k++) a2 += hs[k]*Wd2[k*DD + tid];
        g_demo[b*DD + tid] = a2;
    }
}

// ---------------- head -------------------------------------------------------
__global__ void head_kernel(const float* __restrict__ Wh, const float* __restrict__ bh,
                            float* __restrict__ out)
{
    int b = blockIdx.x;
    int tid = threadIdx.x;                 // 256
    __shared__ float es[256];
    es[tid] = (tid < 128) ? g_ts[b*DD + tid] : g_demo[b*DD + (tid - 128)];
    __syncthreads();
    if (tid < NF) {
        float acc = bh[tid];
#pragma unroll 8
        for (int k = 0; k < 256; k++) acc += es[k]*Wh[k*NF + tid];
        out[b*NF + tid] = acc;
    }
}

// ---------------- orchestration ----------------------------------------------
extern "C" void kernel_launch(void* const* d_in, const int* in_sizes, int n_in,
                              void* d_out, int out_size)
{
    const float* values = (const float*)d_in[0];
    const float* times  = (const float*)d_in[1];
    const int*   vars   = (const int*)d_in[2];
    const void*  maskraw = d_in[3];
    const float* demo   = (const float*)d_in[4];
    const float* W1t = (const float*)d_in[5];
    const float* b1t = (const float*)d_in[6];
    const float* W2t = (const float*)d_in[7];
    const float* W1v = (const float*)d_in[8];
    const float* b1v = (const float*)d_in[9];
    const float* W2v = (const float*)d_in[10];
    const float* vtab = (const float*)d_in[11];
    const float* Wq = (const float*)d_in[12];
    const float* Wk = (const float*)d_in[13];
    const float* Wv = (const float*)d_in[14];
    const float* Wo = (const float*)d_in[15];
    const float* W1 = (const float*)d_in[16];
    const float* b1 = (const float*)d_in[17];
    const float* W2 = (const float*)d_in[18];
    const float* b2 = (const float*)d_in[19];
    const float* Wf = (const float*)d_in[20];
    const float* bf = (const float*)d_in[21];
    const float* uf = (const float*)d_in[22];
    const float* Wd1 = (const float*)d_in[23];
    const float* bd1 = (const float*)d_in[24];
    const float* Wd2 = (const float*)d_in[25];
    const float* bd2 = (const float*)d_in[26];
    const float* Wh = (const float*)d_in[27];
    const float* bh = (const float*)d_in[28];
    float* out = (float*)d_out;

    float *xp, *qkvp, *op, *ffp, *wp;
    cudaGetSymbolAddress((void**)&xp,   g_x);
    cudaGetSymbolAddress((void**)&qkvp, g_qkv);
    cudaGetSymbolAddress((void**)&op,   g_o);
    cudaGetSymbolAddress((void**)&ffp,  g_ff);
    cudaGetSymbolAddress((void**)&wp,   g_w);

    // normalize mask dtype, then compact valid tokens per batch
    mask_reset_kernel<<<1, 32>>>();
    mask_scan_kernel<<<NTOK/4/256, 256>>>((const unsigned int*)maskraw);
    mask_convert_kernel<<<NTOK/256, 256>>>(maskraw);
    compact_kernel<<<BB, 256>>>();

    demo_kernel<<<BB, 256>>>(demo, Wd1, bd1, Wd2, bd2);
    embed_kernel<<<NTOK, 128>>>(values, times, vars, W1t, b1t, W2t, W1v, b1v, W2v, vtab);

    for (int i = 0; i < NLAY; i++) {
        repack_kernel<<<192, 256>>>(Wq + i*HH*DD*DKH, Wk + i*HH*DD*DKH, Wv + i*HH*DD*DKH);
        sgemm_kernel<<<dim3(3, NTOK/128), 256>>>(xp, wp, nullptr, qkvp, 384, 128, 0);
        flash_kernel<<<dim3(SL/128, BB*HH), 128>>>();
        sgemm_kernel<<<dim3(1, NTOK/128), 256>>>(op, Wo + i*DD*DD, nullptr, xp, 128, 128, 1);
        sgemm_kernel<<<dim3(2, NTOK/128), 256>>>(xp, W1 + i*DD*DFF, b1 + i*DFF, ffp, 256, 128, 2);
        sgemm_kernel<<<dim3(1, NTOK/128), 256>>>(ffp, W2 + i*DFF*DD, b2 + i*DD, xp, 128, 256, 3);
    }

    fuse_att_kernel<<<NTOK, 128>>>(Wf, bf, uf);
    pool_kernel<<<BB, 256>>>();
    head_kernel<<<BB, 256>>>(Wh, bh, out);
}

// round 6
// speedup vs baseline: 2.5101x; 1.1390x over previous
#include <cuda_runtime.h>
#include <cuda_bf16.h>
#include <math.h>
#include <stdint.h>

#define BB   16
#define SL   2048
#define DD   128
#define HH   4
#define NLAY 4
#define DKH  32
#define DFF  256
#define NF   129
#define DMG  16
#define INTD 11
#define NTOK (BB*SL)
#define FMIN_F (-3.402823466e38f)

// per-layer transposed bf16 weight planes: qkv[384x128] | wo[128x128] | w1[256x128] | w2[128x256]
#define WT_LAYER 131072
#define WT_QKV   0
#define WT_WO    49152
#define WT_W1    65536
#define WT_W2    98304

// ---------------- scratch (device globals: allocation-free) ----------------
__device__ float g_x[NTOK*DD];
__device__ float g_qkv[NTOK*3*DD];
__device__ float g_o[NTOK*DD];
__device__ float g_ff[NTOK*DFF];
__device__ float g_demo[BB*DD];
__device__ float g_att[BB*SL];
__device__ float g_ts[BB*DD];
__device__ __nv_bfloat16 g_wt0[NLAY*WT_LAYER];
__device__ __nv_bfloat16 g_wt1[NLAY*WT_LAYER];
__device__ __nv_bfloat16 g_wt2[NLAY*WT_LAYER];
__device__ unsigned char g_mask[NTOK];
__device__ int g_idx[NTOK];
__device__ int g_nb[BB];
__device__ int g_npad[BB];
__device__ int g_cnt[2];

// ---------------- PTX helpers -------------------------------------------------
__device__ __forceinline__ uint32_t smem_u32(const void* p) {
    uint32_t a;
    asm("{ .reg .u64 t; cvta.to.shared.u64 t, %1; cvt.u32.u64 %0, t; }" : "=r"(a) : "l"(p));
    return a;
}
__device__ __forceinline__ void ldsm4(uint32_t* r, uint32_t addr) {
    asm volatile("ldmatrix.sync.aligned.m8n8.x4.shared.b16 {%0,%1,%2,%3}, [%4];"
        : "=r"(r[0]), "=r"(r[1]), "=r"(r[2]), "=r"(r[3]) : "r"(addr));
}
__device__ __forceinline__ void mma16816(float* d, const uint32_t* a, const uint32_t* b) {
    asm volatile("mma.sync.aligned.m16n8k16.row.col.f32.bf16.bf16.f32 "
        "{%0,%1,%2,%3}, {%4,%5,%6,%7}, {%8,%9}, {%0,%1,%2,%3};"
        : "+f"(d[0]), "+f"(d[1]), "+f"(d[2]), "+f"(d[3])
        : "r"(a[0]), "r"(a[1]), "r"(a[2]), "r"(a[3]), "r"(b[0]), "r"(b[1]));
}
// 3-way bf16 split of fp32
__device__ __forceinline__ void split3(float x, uint16_t& h0, uint16_t& h1, uint16_t& h2) {
    __nv_bfloat16 b0 = __float2bfloat16(x);
    float r1 = x - __bfloat162float(b0);
    __nv_bfloat16 b1 = __float2bfloat16(r1);
    float r2 = r1 - __bfloat162float(b1);
    __nv_bfloat16 b2 = __float2bfloat16(r2);
    h0 = __bfloat16_as_ushort(b0);
    h1 = __bfloat16_as_ushort(b1);
    h2 = __bfloat16_as_ushort(b2);
}

// ---------------- mask dtype detection + normalization ----------------------
__global__ void mask_reset_kernel() {
    if (threadIdx.x < 2) g_cnt[threadIdx.x] = 0;
}
__global__ void mask_scan_kernel(const unsigned int* __restrict__ w) {
    int i = blockIdx.x*256 + threadIdx.x;
    unsigned int v = w[i];
    if (v > 1u) atomicOr(&g_cnt[0], 1);
    if (v != 0u && v != 0x3F800000u) atomicOr(&g_cnt[1], 1);
}
__global__ void mask_convert_kernel(const void* __restrict__ p) {
    int i = blockIdx.x*256 + threadIdx.x;
    unsigned char m;
    if (g_cnt[0] == 0)       m = (unsigned char)(((const int*)p)[i] != 0);
    else if (g_cnt[1] == 0)  m = (unsigned char)(((const float*)p)[i] != 0.0f);
    else                     m = (unsigned char)(((const unsigned char*)p)[i] != 0);
    g_mask[i] = m;
}

// ---------------- stable compaction ------------------------------------------
__global__ void compact_kernel()
{
    int b = blockIdx.x, tid = threadIdx.x;
    __shared__ int sc[256];
    __shared__ int sbase;
    if (tid == 0) sbase = 0;
    __syncthreads();
    for (int c = 0; c < SL; c += 256) {
        int l = c + tid;
        int m = g_mask[b*SL + l];
        sc[tid] = m;
        __syncthreads();
#pragma unroll
        for (int s = 1; s < 256; s <<= 1) {
            int v = (tid >= s) ? sc[tid - s] : 0;
            __syncthreads();
            sc[tid] += v;
            __syncthreads();
        }
        int pos = sbase + sc[tid] - m;
        if (m) g_idx[b*SL + pos] = l;
        int tot = sc[255];
        __syncthreads();
        if (tid == 0) sbase += tot;
        __syncthreads();
    }
    if (tid == 0) { g_nb[b] = sbase; g_npad[b] = (sbase + 127) & ~127; }
}

// ---------------- embedding (compacted) --------------------------------------
__global__ void embed_kernel(const float* __restrict__ values, const float* __restrict__ times,
                             const int* __restrict__ vars,
                             const float* __restrict__ W1t, const float* __restrict__ b1t,
                             const float* __restrict__ W2t,
                             const float* __restrict__ W1v, const float* __restrict__ b1v,
                             const float* __restrict__ W2v,
                             const float* __restrict__ vtab)
{
    int tok = blockIdx.x;
    int b = tok >> 11, j = tok & 2047;
    int d = threadIdx.x;
    if (j >= g_npad[b]) return;
    if (j >= g_nb[b]) { g_x[(size_t)tok*DD + d] = 0.f; return; }
    int l = g_idx[tok];
    __shared__ float tt[INTD], vv[INTD];
    if (d < INTD) {
        float t = times[b*SL + l], v = values[b*SL + l];
        tt[d] = tanhf(t * W1t[d] + b1t[d]);
        vv[d] = tanhf(v * W1v[d] + b1v[d]);
    }
    __syncthreads();
    int var = vars[b*SL + l];
    float acc = vtab[var*DD + d];
#pragma unroll
    for (int i = 0; i < INTD; i++)
        acc += tt[i]*W2t[i*DD+d] + vv[i]*W2v[i*DD+d];
    g_x[(size_t)tok*DD + d] = acc;
}

// ---------------- weight repack: transpose + bf16 3-way split ----------------
__global__ void wrepack_kernel(const float* __restrict__ Wq, const float* __restrict__ Wk,
                               const float* __restrict__ Wv, const float* __restrict__ Wo,
                               const float* __restrict__ W1, const float* __restrict__ W2)
{
    int idx = blockIdx.x*256 + threadIdx.x;      // < 4*131072
    int layer = idx >> 17;
    int r = idx & (WT_LAYER-1);
    float v;
    if (r < WT_WO) {                 // qkv: n = sel*128+h*32+e, k = d
        int n = r >> 7, k = r & 127;
        int sel = n >> 7;
        int he = n & 127, h = he >> 5, e = he & 31;
        const float* W = sel == 0 ? Wq : (sel == 1 ? Wk : Wv);
        v = W[layer*HH*DD*DKH + h*DD*DKH + k*DKH + e];
    } else if (r < WT_W1) {          // wo: [dout][din]
        int rr = r - WT_WO; int n = rr >> 7, k = rr & 127;
        v = Wo[layer*DD*DD + k*DD + n];
    } else if (r < WT_W2) {          // w1: [f][d]
        int rr = r - WT_W1; int n = rr >> 7, k = rr & 127;
        v = W1[layer*DD*DFF + k*DFF + n];
    } else {                         // w2: [d][f]
        int rr = r - WT_W2; int n = rr >> 8, k = rr & 255;
        v = W2[layer*DFF*DD + k*DD + n];
    }
    uint16_t h0, h1, h2;
    split3(v, h0, h1, h2);
    g_wt0[idx] = __ushort_as_bfloat16(h0);
    g_wt1[idx] = __ushort_as_bfloat16(h1);
    g_wt2[idx] = __ushort_as_bfloat16(h2);
}

// ---------------- HMMA 3-way-split GEMM: C tile 128x128 ----------------------
// epi: 0 none | 1 +=C | 2 bias+gelu | 3 bias+ +=C
#define PLANE 10240                        // 128 rows * 40 cols * 2B
#define TG_SMEM (6*PLANE)

__global__ __launch_bounds__(256)
void tgemm_kernel(const float* __restrict__ A,
                  const __nv_bfloat16* __restrict__ B0,
                  const __nv_bfloat16* __restrict__ B1,
                  const __nv_bfloat16* __restrict__ B2,
                  const float* __restrict__ bias,
                  float* __restrict__ C, int N, int K, int epi)
{
    int bm = blockIdx.y * 128;
    if ((bm & 2047) >= g_npad[bm >> 11]) return;
    int bn = blockIdx.x * 128;

    extern __shared__ char smem[];
    uint16_t (*sA0)[40] = (uint16_t(*)[40])(smem);
    uint16_t (*sA1)[40] = (uint16_t(*)[40])(smem + PLANE);
    uint16_t (*sA2)[40] = (uint16_t(*)[40])(smem + 2*PLANE);
    uint16_t (*sB0)[40] = (uint16_t(*)[40])(smem + 3*PLANE);
    uint16_t (*sB1)[40] = (uint16_t(*)[40])(smem + 4*PLANE);
    uint16_t (*sB2)[40] = (uint16_t(*)[40])(smem + 5*PLANE);

    int tid = threadIdx.x, wid = tid >> 5, lane = tid & 31;
    int wm = (wid & 3) * 32, wn = (wid >> 2) * 64;

    float acc[2][8][4];
#pragma unroll
    for (int mi = 0; mi < 2; mi++)
#pragma unroll
        for (int ni = 0; ni < 8; ni++)
#pragma unroll
            for (int c = 0; c < 4; c++) acc[mi][ni][c] = 0.f;

    uint32_t bA0 = smem_u32(sA0), bA1 = smem_u32(sA1), bA2 = smem_u32(sA2);
    uint32_t bB0 = smem_u32(sB0), bB1 = smem_u32(sB1), bB2 = smem_u32(sB2);
    int rowA = lane & 15, colA8 = (lane >> 4) * 8;
    int rowB = ((lane >> 4) << 3) + (lane & 7), colB8 = ((lane >> 3) & 1) * 8;

    for (int k0 = 0; k0 < K; k0 += 32) {
        // stage A: fp32 -> 3-way bf16 split
#pragma unroll
        for (int it = 0; it < 4; it++) {
            int idx = tid + it*256;             // 1024 float4-groups
            int row = idx >> 3, c4 = (idx & 7) * 4;
            float4 a = *(const float4*)(A + (size_t)(bm + row)*K + k0 + c4);
            float av[4] = {a.x, a.y, a.z, a.w};
            uint16_t p0[4], p1[4], p2[4];
#pragma unroll
            for (int u = 0; u < 4; u++) split3(av[u], p0[u], p1[u], p2[u]);
            *(uint2*)&sA0[row][c4] = *(uint2*)p0;
            *(uint2*)&sA1[row][c4] = *(uint2*)p1;
            *(uint2*)&sA2[row][c4] = *(uint2*)p2;
        }
        // stage B planes (precomputed bf16)
#pragma unroll
        for (int it = 0; it < 4; it++) {
            int idx = tid + it*256;
            int row = idx >> 3, c4 = (idx & 7) * 4;
            size_t goff = (size_t)(bn + row)*K + k0 + c4;
            *(uint2*)&sB0[row][c4] = *(const uint2*)(B0 + goff);
            *(uint2*)&sB1[row][c4] = *(const uint2*)(B1 + goff);
            *(uint2*)&sB2[row][c4] = *(const uint2*)(B2 + goff);
        }
        __syncthreads();

#pragma unroll
        for (int ks = 0; ks < 32; ks += 16) {
            uint32_t a0[2][4], a1[2][4], a2[2][4];
#pragma unroll
            for (int mi = 0; mi < 2; mi++) {
                uint32_t off = ((uint32_t)((wm + mi*16 + rowA)*40 + ks + colA8)) * 2;
                ldsm4(a0[mi], bA0 + off);
                ldsm4(a1[mi], bA1 + off);
                ldsm4(a2[mi], bA2 + off);
            }
#pragma unroll
            for (int pi = 0; pi < 4; pi++) {
                uint32_t off = ((uint32_t)((wn + pi*16 + rowB)*40 + ks + colB8)) * 2;
                uint32_t b0[4], b1[4], b2[4];
                ldsm4(b0, bB0 + off);
                ldsm4(b1, bB1 + off);
                ldsm4(b2, bB2 + off);
#pragma unroll
                for (int mi = 0; mi < 2; mi++)
#pragma unroll
                    for (int nj = 0; nj < 2; nj++) {
                        float* ac = acc[mi][pi*2 + nj];
                        const uint32_t* f0 = &b0[nj*2];
                        const uint32_t* f1 = &b1[nj*2];
                        const uint32_t* f2 = &b2[nj*2];
                        mma16816(ac, a0[mi], f0);     // a0*b0
                        mma16816(ac, a0[mi], f1);     // a0*b1
                        mma16816(ac, a1[mi], f0);     // a1*b0
                        mma16816(ac, a0[mi], f2);     // a0*b2
                        mma16816(ac, a1[mi], f1);     // a1*b1
                        mma16816(ac, a2[mi], f0);     // a2*b0
                    }
            }
        }
        __syncthreads();
    }

    // epilogue
    int r0base = bm + wm + (lane >> 2);
    int cbase = wn + (lane & 3) * 2;
#pragma unroll
    for (int mi = 0; mi < 2; mi++) {
#pragma unroll
        for (int ni = 0; ni < 8; ni++) {
            int col = bn + cbase + ni*8;
#pragma unroll
            for (int half = 0; half < 2; half++) {
                int row = r0base + mi*16 + half*8;
                float v0 = acc[mi][ni][half*2], v1 = acc[mi][ni][half*2+1];
                float* Cp = C + (size_t)row*N + col;
                if (epi >= 2) {
                    v0 += bias[col]; v1 += bias[col+1];
                }
                if (epi == 2) {
                    v0 = 0.5f*v0*(1.f + erff(v0*0.7071067811865476f));
                    v1 = 0.5f*v1*(1.f + erff(v1*0.7071067811865476f));
                }
                if (epi == 1 || epi == 3) {
                    float2 o = *(const float2*)Cp;
                    v0 += o.x; v1 += o.y;
                }
                *(float2*)Cp = make_float2(v0, v1);
            }
        }
    }
}

// ---------------- flash attention over compacted tokens ---------------------
__global__ __launch_bounds__(128)
void flash_kernel()
{
    const int KB = 64;
    int bh = blockIdx.y;
    int b = bh >> 2, h = bh & 3;
    int n = g_nb[b];
    if ((int)(blockIdx.x*128) >= n) return;
    int j = blockIdx.x*128 + threadIdx.x;
    __shared__ float Ks[KB][DKH];
    __shared__ float Vs[KB][DKH];

    float qv[DKH];
    const float* qptr = g_qkv + (size_t)(b*SL + j)*384 + h*32;
#pragma unroll
    for (int e = 0; e < DKH; e += 4) {
        float4 f = *(const float4*)(qptr + e);
        qv[e] = f.x; qv[e+1] = f.y; qv[e+2] = f.z; qv[e+3] = f.w;
    }
    float mx = -INFINITY, lsum = 0.f;
    float acc[DKH];
#pragma unroll
    for (int e = 0; e < DKH; e++) acc[e] = 0.f;

    int tid = threadIdx.x;
    for (int k0 = 0; k0 < n; k0 += KB) {
#pragma unroll
        for (int it = 0; it < 4; it++) {
            int v = tid + it*128;
            int row = v >> 3, c4 = (v & 7) * 4;
            const float* base = g_qkv + (size_t)(b*SL + k0 + row)*384 + h*32;
            *(float4*)&Ks[row][c4] = *(const float4*)(base + 128 + c4);
            *(float4*)&Vs[row][c4] = *(const float4*)(base + 256 + c4);
        }
        __syncthreads();

#pragma unroll 4
        for (int jj = 0; jj < KB; jj++) {
            float d0=0.f, d1=0.f, d2=0.f, d3=0.f;
#pragma unroll
            for (int e = 0; e < DKH; e += 4) {
                d0 += qv[e]  *Ks[jj][e];
                d1 += qv[e+1]*Ks[jj][e+1];
                d2 += qv[e+2]*Ks[jj][e+2];
                d3 += qv[e+3]*Ks[jj][e+3];
            }
            float s = (k0 + jj < n) ? ((d0+d1)+(d2+d3)) : FMIN_F;
            if (s > mx) {
                float c = __expf(mx - s);
                lsum *= c;
#pragma unroll
                for (int e = 0; e < DKH; e++) acc[e] *= c;
                mx = s;
            }
            float p = __expf(s - mx);
            lsum += p;
#pragma unroll
            for (int e = 0; e < DKH; e++) acc[e] += p*Vs[jj][e];
        }
        __syncthreads();
    }
    float inv = 1.f / lsum;
    float* optr = g_o + (size_t)(b*SL + j)*DD + h*32;
#pragma unroll
    for (int e = 0; e < DKH; e++) optr[e] = acc[e]*inv;
}

// ---------------- fusion attention logits ------------------------------------
__global__ void fuse_att_kernel(const float* __restrict__ Wf, const float* __restrict__ bf,
                                const float* __restrict__ uf)
{
    int tok = blockIdx.x;
    int b = tok >> 11, j = tok & 2047;
    if (j >= g_nb[b]) return;
    int d = threadIdx.x;
    __shared__ float xs[DD];
    __shared__ float red[128];
    xs[d] = g_x[(size_t)tok*DD + d];
    __syncthreads();
    float acc = bf[d];
#pragma unroll 8
    for (int k = 0; k < DD; k++) acc += xs[k]*Wf[k*DD + d];
    red[d] = tanhf(acc)*uf[d];
    __syncthreads();
    for (int s = 64; s > 0; s >>= 1) {
        if (d < s) red[d] += red[d + s];
        __syncthreads();
    }
    if (d == 0) g_att[tok] = red[0];
}

// ---------------- masked softmax pooling -------------------------------------
__global__ void pool_kernel()
{
    int b = blockIdx.x;
    int n = g_nb[b];
    int tid = threadIdx.x;
    __shared__ float w[SL];
    __shared__ float red[256];
    float mx = -INFINITY;
    for (int l = tid; l < n; l += 256) mx = fmaxf(mx, g_att[b*SL + l]);
    red[tid] = mx; __syncthreads();
    for (int s = 128; s > 0; s >>= 1) { if (tid < s) red[tid] = fmaxf(red[tid], red[tid+s]); __syncthreads(); }
    mx = red[0]; __syncthreads();
    float sum = 0.f;
    for (int l = tid; l < n; l += 256) { float e = __expf(g_att[b*SL+l] - mx); w[l] = e; sum += e; }
    red[tid] = sum; __syncthreads();
    for (int s = 128; s > 0; s >>= 1) { if (tid < s) red[tid] += red[tid+s]; __syncthreads(); }
    float inv = 1.f / red[0];
    __syncthreads();
    int d = tid & 127, half = tid >> 7;
    float acc = 0.f;
    for (int l = half; l < n; l += 2)
        acc += w[l]*g_x[((size_t)b*SL + l)*DD + d];
    red[tid] = acc; __syncthreads();
    if (tid < 128) g_ts[b*DD + tid] = (red[tid] + red[tid+128])*inv;
}

// ---------------- demographics MLP -------------------------------------------
__global__ void demo_kernel(const float* __restrict__ demo, const float* __restrict__ Wd1,
                            const float* __restrict__ bd1, const float* __restrict__ Wd2,
                            const float* __restrict__ bd2)
{
    int b = blockIdx.x;
    int tid = threadIdx.x;
    __shared__ float ds[DMG];
    __shared__ float hs[256];
    if (tid < DMG) ds[tid] = demo[b*DMG + tid];
    __syncthreads();
    float a = bd1[tid];
#pragma unroll
    for (int k = 0; k < DMG; k++) a += ds[k]*Wd1[k*256 + tid];
    hs[tid] = tanhf(a);
    __syncthreads();
    if (tid < DD) {
        float a2 = bd2[tid];
#pragma unroll 8
        for (int k = 0; k < 256; k++) a2 += hs[k]*Wd2[k*DD + tid];
        g_demo[b*DD + tid] = a2;
    }
}

// ---------------- head --------------------------------------------------------
__global__ void head_kernel(const float* __restrict__ Wh, const float* __restrict__ bh,
                            float* __restrict__ out)
{
    int b = blockIdx.x;
    int tid = threadIdx.x;
    __shared__ float es[256];
    es[tid] = (tid < 128) ? g_ts[b*DD + tid] : g_demo[b*DD + (tid - 128)];
    __syncthreads();
    if (tid < NF) {
        float acc = bh[tid];
#pragma unroll 8
        for (int k = 0; k < 256; k++) acc += es[k]*Wh[k*NF + tid];
        out[b*NF + tid] = acc;
    }
}

// ---------------- orchestration ------------------------------------------------
extern "C" void kernel_launch(void* const* d_in, const int* in_sizes, int n_in,
                              void* d_out, int out_size)
{
    const float* values = (const float*)d_in[0];
    const float* times  = (const float*)d_in[1];
    const int*   vars   = (const int*)d_in[2];
    const void*  maskraw = d_in[3];
    const float* demo   = (const float*)d_in[4];
    const float* W1t = (const float*)d_in[5];
    const float* b1t = (const float*)d_in[6];
    const float* W2t = (const float*)d_in[7];
    const float* W1v = (const float*)d_in[8];
    const float* b1v = (const float*)d_in[9];
    const float* W2v = (const float*)d_in[10];
    const float* vtab = (const float*)d_in[11];
    const float* Wq = (const float*)d_in[12];
    const float* Wk = (const float*)d_in[13];
    const float* Wv = (const float*)d_in[14];
    const float* Wo = (const float*)d_in[15];
    const float* W1 = (const float*)d_in[16];
    const float* b1 = (const float*)d_in[17];
    const float* W2 = (const float*)d_in[18];
    const float* b2 = (const float*)d_in[19];
    const float* Wf = (const float*)d_in[20];
    const float* bf = (const float*)d_in[21];
    const float* uf = (const float*)d_in[22];
    const float* Wd1 = (const float*)d_in[23];
    const float* bd1 = (const float*)d_in[24];
    const float* Wd2 = (const float*)d_in[25];
    const float* bd2 = (const float*)d_in[26];
    const float* Wh = (const float*)d_in[27];
    const float* bh = (const float*)d_in[28];
    float* out = (float*)d_out;

    float *xp, *qkvp, *op, *ffp;
    __nv_bfloat16 *w0p, *w1p, *w2p;
    cudaGetSymbolAddress((void**)&xp,   g_x);
    cudaGetSymbolAddress((void**)&qkvp, g_qkv);
    cudaGetSymbolAddress((void**)&op,   g_o);
    cudaGetSymbolAddress((void**)&ffp,  g_ff);
    cudaGetSymbolAddress((void**)&w0p,  g_wt0);
    cudaGetSymbolAddress((void**)&w1p,  g_wt1);
    cudaGetSymbolAddress((void**)&w2p,  g_wt2);

    cudaFuncSetAttribute(tgemm_kernel, cudaFuncAttributeMaxDynamicSharedMemorySize, TG_SMEM);

    // normalize mask dtype, compact valid tokens per batch
    mask_reset_kernel<<<1, 32>>>();
    mask_scan_kernel<<<NTOK/4/256, 256>>>((const unsigned int*)maskraw);
    mask_convert_kernel<<<NTOK/256, 256>>>(maskraw);
    compact_kernel<<<BB, 256>>>();

    wrepack_kernel<<<NLAY*WT_LAYER/256, 256>>>(Wq, Wk, Wv, Wo, W1, W2);
    demo_kernel<<<BB, 256>>>(demo, Wd1, bd1, Wd2, bd2);
    embed_kernel<<<NTOK, 128>>>(values, times, vars, W1t, b1t, W2t, W1v, b1v, W2v, vtab);

    for (int i = 0; i < NLAY; i++) {
        const __nv_bfloat16* l0 = w0p + i*WT_LAYER;
        const __nv_bfloat16* l1 = w1p + i*WT_LAYER;
        const __nv_bfloat16* l2 = w2p + i*WT_LAYER;
        tgemm_kernel<<<dim3(3, NTOK/128), 256, TG_SMEM>>>(xp, l0 + WT_QKV, l1 + WT_QKV, l2 + WT_QKV,
                                                          nullptr, qkvp, 384, 128, 0);
        flash_kernel<<<dim3(SL/128, BB*HH), 128>>>();
        tgemm_kernel<<<dim3(1, NTOK/128), 256, TG_SMEM>>>(op, l0 + WT_WO, l1 + WT_WO, l2 + WT_WO,
                                                          nullptr, xp, 128, 128, 1);
        tgemm_kernel<<<dim3(2, NTOK/128), 256, TG_SMEM>>>(xp, l0 + WT_W1, l1 + WT_W1, l2 + WT_W1,
                                                          b1 + i*DFF, ffp, 256, 128, 2);
        tgemm_kernel<<<dim3(1, NTOK/128), 256, TG_SMEM>>>(ffp, l0 + WT_W2, l1 + WT_W2, l2 + WT_W2,
                                                          b2 + i*DD, xp, 128, 256, 3);
    }

    fuse_att_kernel<<<NTOK, 128>>>(Wf, bf, uf);
    pool_kernel<<<BB, 256>>>();
    head_kernel<<<BB, 256>>>(Wh, bh, out);
}

// round 10
// speedup vs baseline: 4.2128x; 1.6783x over previous
#include <cuda_runtime.h>
#include <cuda_bf16.h>
#include <math.h>
#include <stdint.h>

#define BB   16
#define SL   2048
#define DD   128
#define HH   4
#define NLAY 4
#define DKH  32
#define DFF  256
#define NF   129
#define DMG  16
#define INTD 11
#define NTOK (BB*SL)
#define FMIN_F (-3.402823466e38f)

// per-layer transposed bf16 weight planes: qkv[384x128] | wo[128x128] | w1[256x128] | w2[128x256]
#define WT_LAYER 131072
#define WT_QKV   0
#define WT_WO    49152
#define WT_W1    65536
#define WT_W2    98304

// ---------------- scratch (device globals: allocation-free) ----------------
__device__ float g_x[NTOK*DD];
__device__ float g_qkv[NTOK*3*DD];
__device__ float g_o[NTOK*DD];
__device__ float g_ff[NTOK*DFF];
__device__ float g_demo[BB*DD];
__device__ float g_att[BB*SL];
__device__ float g_ts[BB*DD];
__device__ __nv_bfloat16 g_wt0[NLAY*WT_LAYER];
__device__ __nv_bfloat16 g_wt1[NLAY*WT_LAYER];
__device__ __nv_bfloat16 g_wt2[NLAY*WT_LAYER];
// per-(b,h) split planes of K (3) and V (2): [((b*4+h)*SL + j)*32 + e]
#define PL_ELEMS (BB*HH*SL*DKH)
__device__ __nv_bfloat16 g_k0[PL_ELEMS];
__device__ __nv_bfloat16 g_k1[PL_ELEMS];
__device__ __nv_bfloat16 g_k2[PL_ELEMS];
__device__ __nv_bfloat16 g_v0[PL_ELEMS];
__device__ __nv_bfloat16 g_v1[PL_ELEMS];
__device__ unsigned char g_mask[NTOK];
__device__ int g_idx[NTOK];
__device__ int g_nb[BB];
__device__ int g_npad[BB];
__device__ int g_cnt[2];

// ---------------- PTX helpers -------------------------------------------------
__device__ __forceinline__ uint32_t smem_u32(const void* p) {
    uint32_t a;
    asm("{ .reg .u64 t; cvta.to.shared.u64 t, %1; cvt.u32.u64 %0, t; }" : "=r"(a) : "l"(p));
    return a;
}
__device__ __forceinline__ void ldsm4(uint32_t* r, uint32_t addr) {
    asm volatile("ldmatrix.sync.aligned.m8n8.x4.shared.b16 {%0,%1,%2,%3}, [%4];"
        : "=r"(r[0]), "=r"(r[1]), "=r"(r[2]), "=r"(r[3]) : "r"(addr));
}
__device__ __forceinline__ void ldsm4t(uint32_t* r, uint32_t addr) {
    asm volatile("ldmatrix.sync.aligned.m8n8.x4.trans.shared.b16 {%0,%1,%2,%3}, [%4];"
        : "=r"(r[0]), "=r"(r[1]), "=r"(r[2]), "=r"(r[3]) : "r"(addr));
}
__device__ __forceinline__ void mma16816(float* d, const uint32_t* a, const uint32_t* b) {
    asm volatile("mma.sync.aligned.m16n8k16.row.col.f32.bf16.bf16.f32 "
        "{%0,%1,%2,%3}, {%4,%5,%6,%7}, {%8,%9}, {%0,%1,%2,%3};"
        : "+f"(d[0]), "+f"(d[1]), "+f"(d[2]), "+f"(d[3])
        : "r"(a[0]), "r"(a[1]), "r"(a[2]), "r"(a[3]), "r"(b[0]), "r"(b[1]));
}
// RN 3-way split (weights, Q, K, P)
__device__ __forceinline__ void split3(float x, uint16_t& h0, uint16_t& h1, uint16_t& h2) {
    __nv_bfloat16 b0 = __float2bfloat16(x);
    float r1 = x - __bfloat162float(b0);
    __nv_bfloat16 b1 = __float2bfloat16(r1);
    float r2 = r1 - __bfloat162float(b1);
    __nv_bfloat16 b2 = __float2bfloat16(r2);
    h0 = __bfloat16_as_ushort(b0);
    h1 = __bfloat16_as_ushort(b1);
    h2 = __bfloat16_as_ushort(b2);
}
// RN 2-way split (V)
__device__ __forceinline__ void split2(float x, uint16_t& h0, uint16_t& h1) {
    __nv_bfloat16 b0 = __float2bfloat16(x);
    float r1 = x - __bfloat162float(b0);
    __nv_bfloat16 b1 = __float2bfloat16(r1);
    h0 = __bfloat16_as_ushort(b0);
    h1 = __bfloat16_as_ushort(b1);
}
__device__ __forceinline__ uint32_t pack16(uint16_t lo, uint16_t hi) {
    return (uint32_t)lo | ((uint32_t)hi << 16);
}

// ---------------- mask dtype detection + normalization ----------------------
__global__ void mask_reset_kernel() {
    if (threadIdx.x < 2) g_cnt[threadIdx.x] = 0;
}
__global__ void mask_scan_kernel(const unsigned int* __restrict__ w) {
    int i = blockIdx.x*256 + threadIdx.x;
    unsigned int v = w[i];
    if (v > 1u) atomicOr(&g_cnt[0], 1);
    if (v != 0u && v != 0x3F800000u) atomicOr(&g_cnt[1], 1);
}
__global__ void mask_convert_kernel(const void* __restrict__ p) {
    int i = blockIdx.x*256 + threadIdx.x;
    unsigned char m;
    if (g_cnt[0] == 0)       m = (unsigned char)(((const int*)p)[i] != 0);
    else if (g_cnt[1] == 0)  m = (unsigned char)(((const float*)p)[i] != 0.0f);
    else                     m = (unsigned char)(((const unsigned char*)p)[i] != 0);
    g_mask[i] = m;
}

// ---------------- stable compaction ------------------------------------------
__global__ void compact_kernel()
{
    int b = blockIdx.x, tid = threadIdx.x;
    __shared__ int sc[256];
    __shared__ int sbase;
    if (tid == 0) sbase = 0;
    __syncthreads();
    for (int c = 0; c < SL; c += 256) {
        int l = c + tid;
        int m = g_mask[b*SL + l];
        sc[tid] = m;
        __syncthreads();
#pragma unroll
        for (int s = 1; s < 256; s <<= 1) {
            int v = (tid >= s) ? sc[tid - s] : 0;
            __syncthreads();
            sc[tid] += v;
            __syncthreads();
        }
        int pos = sbase + sc[tid] - m;
        if (m) g_idx[b*SL + pos] = l;
        int tot = sc[255];
        __syncthreads();
        if (tid == 0) sbase += tot;
        __syncthreads();
    }
    if (tid == 0) { g_nb[b] = sbase; g_npad[b] = (sbase + 127) & ~127; }
}

// ---------------- embedding (compacted) --------------------------------------
__global__ void embed_kernel(const float* __restrict__ values, const float* __restrict__ times,
                             const int* __restrict__ vars,
                             const float* __restrict__ W1t, const float* __restrict__ b1t,
                             const float* __restrict__ W2t,
                             const float* __restrict__ W1v, const float* __restrict__ b1v,
                             const float* __restrict__ W2v,
                             const float* __restrict__ vtab)
{
    int tok = blockIdx.x;
    int b = tok >> 11, j = tok & 2047;
    int d = threadIdx.x;
    if (j >= g_npad[b]) return;
    if (j >= g_nb[b]) { g_x[(size_t)tok*DD + d] = 0.f; return; }
    int l = g_idx[tok];
    __shared__ float tt[INTD], vv[INTD];
    if (d < INTD) {
        float t = times[b*SL + l], v = values[b*SL + l];
        tt[d] = tanhf(t * W1t[d] + b1t[d]);
        vv[d] = tanhf(v * W1v[d] + b1v[d]);
    }
    __syncthreads();
    int var = vars[b*SL + l];
    float acc = vtab[var*DD + d];
#pragma unroll
    for (int i = 0; i < INTD; i++)
        acc += tt[i]*W2t[i*DD+d] + vv[i]*W2v[i*DD+d];
    g_x[(size_t)tok*DD + d] = acc;
}

// ---------------- weight repack: transpose + bf16 3-way split ----------------
__global__ void wrepack_kernel(const float* __restrict__ Wq, const float* __restrict__ Wk,
                               const float* __restrict__ Wv, const float* __restrict__ Wo,
                               const float* __restrict__ W1, const float* __restrict__ W2)
{
    int idx = blockIdx.x*256 + threadIdx.x;      // < 4*131072
    int layer = idx >> 17;
    int r = idx & (WT_LAYER-1);
    float v;
    if (r < WT_WO) {                 // qkv: n = sel*128+h*32+e, k = d
        int n = r >> 7, k = r & 127;
        int sel = n >> 7;
        int he = n & 127, h = he >> 5, e = he & 31;
        const float* W = sel == 0 ? Wq : (sel == 1 ? Wk : Wv);
        v = W[layer*HH*DD*DKH + h*DD*DKH + k*DKH + e];
    } else if (r < WT_W1) {          // wo: [dout][din]
        int rr = r - WT_WO; int n = rr >> 7, k = rr & 127;
        v = Wo[layer*DD*DD + k*DD + n];
    } else if (r < WT_W2) {          // w1: [f][d]
        int rr = r - WT_W1; int n = rr >> 7, k = rr & 127;
        v = W1[layer*DD*DFF + k*DFF + n];
    } else {                         // w2: [d][f]
        int rr = r - WT_W2; int n = rr >> 8, k = rr & 255;
        v = W2[layer*DFF*DD + k*DD + n];
    }
    uint16_t h0, h1, h2;
    split3(v, h0, h1, h2);
    g_wt0[idx] = __ushort_as_bfloat16(h0);
    g_wt1[idx] = __ushort_as_bfloat16(h1);
    g_wt2[idx] = __ushort_as_bfloat16(h2);
}

// ---------------- HMMA 3-way-split GEMM: C tile 128x128 ----------------------
// epi: 0 none | 1 +=C | 2 bias+gelu | 3 bias+ +=C
#define PLANE 10240                        // 128 rows * 40 cols * 2B (tgemm planes)
#define TG_SMEM (6*PLANE)

__global__ __launch_bounds__(256)
void tgemm_kernel(const float* __restrict__ A,
                  const __nv_bfloat16* __restrict__ B0,
                  const __nv_bfloat16* __restrict__ B1,
                  const __nv_bfloat16* __restrict__ B2,
                  const float* __restrict__ bias,
                  float* __restrict__ C, int N, int K, int epi)
{
    int bm = blockIdx.y * 128;
    if ((bm & 2047) >= g_npad[bm >> 11]) return;
    int bn = blockIdx.x * 128;

    extern __shared__ char smem[];
    uint16_t (*sA0)[40] = (uint16_t(*)[40])(smem);
    uint16_t (*sA1)[40] = (uint16_t(*)[40])(smem + PLANE);
    uint16_t (*sA2)[40] = (uint16_t(*)[40])(smem + 2*PLANE);
    uint16_t (*sB0)[40] = (uint16_t(*)[40])(smem + 3*PLANE);
    uint16_t (*sB1)[40] = (uint16_t(*)[40])(smem + 4*PLANE);
    uint16_t (*sB2)[40] = (uint16_t(*)[40])(smem + 5*PLANE);

    int tid = threadIdx.x, wid = tid >> 5, lane = tid & 31;
    int wm = (wid & 3) * 32, wn = (wid >> 2) * 64;

    float acc[2][8][4];
#pragma unroll
    for (int mi = 0; mi < 2; mi++)
#pragma unroll
        for (int ni = 0; ni < 8; ni++)
#pragma unroll
            for (int c = 0; c < 4; c++) acc[mi][ni][c] = 0.f;

    uint32_t bA0 = smem_u32(sA0), bA1 = smem_u32(sA1), bA2 = smem_u32(sA2);
    uint32_t bB0 = smem_u32(sB0), bB1 = smem_u32(sB1), bB2 = smem_u32(sB2);
    int rowA = lane & 15, colA8 = (lane >> 4) * 8;
    int rowB = ((lane >> 4) << 3) + (lane & 7), colB8 = ((lane >> 3) & 1) * 8;

    for (int k0 = 0; k0 < K; k0 += 32) {
#pragma unroll
        for (int it = 0; it < 4; it++) {
            int idx = tid + it*256;             // 1024 float4-groups
            int row = idx >> 3, c4 = (idx & 7) * 4;
            float4 a = *(const float4*)(A + (size_t)(bm + row)*K + k0 + c4);
            float av[4] = {a.x, a.y, a.z, a.w};
            uint16_t p0[4], p1[4], p2[4];
#pragma unroll
            for (int u = 0; u < 4; u++) split3(av[u], p0[u], p1[u], p2[u]);
            *(uint2*)&sA0[row][c4] = *(uint2*)p0;
            *(uint2*)&sA1[row][c4] = *(uint2*)p1;
            *(uint2*)&sA2[row][c4] = *(uint2*)p2;
        }
#pragma unroll
        for (int it = 0; it < 4; it++) {
            int idx = tid + it*256;
            int row = idx >> 3, c4 = (idx & 7) * 4;
            size_t goff = (size_t)(bn + row)*K + k0 + c4;
            *(uint2*)&sB0[row][c4] = *(const uint2*)(B0 + goff);
            *(uint2*)&sB1[row][c4] = *(const uint2*)(B1 + goff);
            *(uint2*)&sB2[row][c4] = *(const uint2*)(B2 + goff);
        }
        __syncthreads();

#pragma unroll
        for (int ks = 0; ks < 32; ks += 16) {
            uint32_t a0[2][4], a1[2][4], a2[2][4];
#pragma unroll
            for (int mi = 0; mi < 2; mi++) {
                uint32_t off = ((uint32_t)((wm + mi*16 + rowA)*40 + ks + colA8)) * 2;
                ldsm4(a0[mi], bA0 + off);
                ldsm4(a1[mi], bA1 + off);
                ldsm4(a2[mi], bA2 + off);
            }
#pragma unroll
            for (int pi = 0; pi < 4; pi++) {
                uint32_t off = ((uint32_t)((wn + pi*16 + rowB)*40 + ks + colB8)) * 2;
                uint32_t b0[4], b1[4], b2[4];
                ldsm4(b0, bB0 + off);
                ldsm4(b1, bB1 + off);
                ldsm4(b2, bB2 + off);
#pragma unroll
                for (int mi = 0; mi < 2; mi++)
#pragma unroll
                    for (int nj = 0; nj < 2; nj++) {
                        float* ac = acc[mi][pi*2 + nj];
                        const uint32_t* f0 = &b0[nj*2];
                        const uint32_t* f1 = &b1[nj*2];
                        const uint32_t* f2 = &b2[nj*2];
                        mma16816(ac, a0[mi], f0);
                        mma16816(ac, a0[mi], f1);
                        mma16816(ac, a1[mi], f0);
                        mma16816(ac, a0[mi], f2);
                        mma16816(ac, a1[mi], f1);
                        mma16816(ac, a2[mi], f0);
                    }
            }
        }
        __syncthreads();
    }

    int r0base = bm + wm + (lane >> 2);
    int cbase = wn + (lane & 3) * 2;
#pragma unroll
    for (int mi = 0; mi < 2; mi++) {
#pragma unroll
        for (int ni = 0; ni < 8; ni++) {
            int col = bn + cbase + ni*8;
#pragma unroll
            for (int half = 0; half < 2; half++) {
                int row = r0base + mi*16 + half*8;
                float v0 = acc[mi][ni][half*2], v1 = acc[mi][ni][half*2+1];
                float* Cp = C + (size_t)row*N + col;
                if (epi >= 2) {
                    v0 += bias[col]; v1 += bias[col+1];
                }
                if (epi == 2) {
                    v0 = 0.5f*v0*(1.f + erff(v0*0.7071067811865476f));
                    v1 = 0.5f*v1*(1.f + erff(v1*0.7071067811865476f));
                }
                if (epi == 1 || epi == 3) {
                    float2 o = *(const float2*)Cp;
                    v0 += o.x; v1 += o.y;
                }
                *(float2*)Cp = make_float2(v0, v1);
            }
        }
    }
}

// ---------------- K/V plane split (once per layer, RN splits) ----------------
__global__ void qkvsplit_kernel()
{
    int idx = blockIdx.x*256 + threadIdx.x;   // NTOK*32 threads, 8 elems each
    int tok = idx >> 5;
    int grp = idx & 31;
    int b = tok >> 11, j = tok & 2047;
    if (j >= g_npad[b]) return;
    int sel = grp >> 4;                        // 0=K, 1=V
    int h = (grp >> 2) & 3;
    int e = (grp & 3) * 8;
    const float* src = g_qkv + (size_t)tok*384 + 128 + sel*128 + h*32 + e;
    float4 f0 = *(const float4*)src;
    float4 f1 = *(const float4*)(src + 4);
    float v[8] = {f0.x, f0.y, f0.z, f0.w, f1.x, f1.y, f1.z, f1.w};
    size_t dst = ((size_t)(b*4 + h)*SL + j)*32 + e;
    if (sel == 0) {
        uint16_t p0[8], p1[8], p2[8];
#pragma unroll
        for (int u = 0; u < 8; u++) split3(v[u], p0[u], p1[u], p2[u]);
        *(uint4*)(g_k0 + dst) = *(uint4*)p0;
        *(uint4*)(g_k1 + dst) = *(uint4*)p1;
        *(uint4*)(g_k2 + dst) = *(uint4*)p2;
    } else {
        uint16_t p0[8], p1[8];
#pragma unroll
        for (int u = 0; u < 8; u++) split2(v[u], p0[u], p1[u]);
        *(uint4*)(g_v0 + dst) = *(uint4*)p0;
        *(uint4*)(g_v1 + dst) = *(uint4*)p1;
    }
}

// ---------------- HMMA flash attention ---------------------------------------
// block: 4 warps, 64 queries x one (b,h); key tiles of 64
#define KPLANE (64*40*2)   // intra-array plane stride of sQ/sK/sV

__global__ __launch_bounds__(128)
void flash_kernel()
{
    int bh = blockIdx.y;
    int b = bh >> 2, h = bh & 3;
    int n = g_nb[b];
    int q0 = blockIdx.x * 64;
    if (q0 >= n) return;

    __shared__ __align__(16) uint16_t sQ[3][64][40];
    __shared__ __align__(16) uint16_t sK[3][64][40];
    __shared__ __align__(16) uint16_t sV[2][64][40];

    int tid = threadIdx.x, wid = tid >> 5, lane = tid & 31;

    // ---- stage Q (fp32 -> RN 3-plane split) ----
#pragma unroll
    for (int it = 0; it < 4; it++) {
        int idx = tid + it*128;                 // 512 float4-groups
        int row = idx >> 3, c4 = (idx & 7) * 4;
        float4 f = *(const float4*)(g_qkv + (size_t)(b*SL + q0 + row)*384 + h*32 + c4);
        float av[4] = {f.x, f.y, f.z, f.w};
        uint16_t p0[4], p1[4], p2[4];
#pragma unroll
        for (int u = 0; u < 4; u++) split3(av[u], p0[u], p1[u], p2[u]);
        *(uint2*)&sQ[0][row][c4] = *(uint2*)p0;
        *(uint2*)&sQ[1][row][c4] = *(uint2*)p1;
        *(uint2*)&sQ[2][row][c4] = *(uint2*)p2;
    }
    __syncthreads();

    // Q fragments held in registers for the whole kernel
    uint32_t qf[3][2][4];
    int rowA = lane & 15, colA8 = (lane >> 4) * 8;
#pragma unroll
    for (int p = 0; p < 3; p++)
#pragma unroll
        for (int ks = 0; ks < 2; ks++)
            ldsm4(qf[p][ks], smem_u32(&sQ[p][wid*16 + rowA][ks*16 + colA8]));

    float mx[2] = {-INFINITY, -INFINITY};
    float ls[2] = {0.f, 0.f};
    float oa[4][4];
#pragma unroll
    for (int i = 0; i < 4; i++)
#pragma unroll
        for (int u = 0; u < 4; u++) oa[i][u] = 0.f;

    int rowB = ((lane >> 4) << 3) + (lane & 7), colB8 = ((lane >> 3) & 1) * 8;

    for (int k0 = 0; k0 < n; k0 += 64) {
        __syncthreads();
        // ---- stage K/V planes (pure vectorized copies) ----
#pragma unroll
        for (int it = 0; it < 10; it++) {
            int idx = tid + it*128;             // 1280 uint4
            int plane = idx >> 8;               // 0..4
            int r = (idx >> 2) & 63;
            int e8 = (idx & 3) * 8;
            const __nv_bfloat16* src =
                plane == 0 ? g_k0 : plane == 1 ? g_k1 : plane == 2 ? g_k2 :
                plane == 3 ? g_v0 : g_v1;
            uint4 val = *(const uint4*)(src + ((size_t)bh*SL + k0 + r)*32 + e8);
            uint16_t* dst = plane < 3 ? &sK[plane][r][e8] : &sV[plane-3][r][e8];
            *(uint4*)dst = val;
        }
        __syncthreads();

        // ---- S = Q K^T (8-product RN split) ----
        float sf[8][4];
#pragma unroll
        for (int j = 0; j < 8; j++)
#pragma unroll
            for (int u = 0; u < 4; u++) sf[j][u] = 0.f;

#pragma unroll
        for (int ks = 0; ks < 2; ks++) {
#pragma unroll
            for (int i = 0; i < 4; i++) {       // n16 key groups
                uint32_t off0 = smem_u32(&sK[0][i*16 + rowB][ks*16 + colB8]);
                uint32_t kb0[4], kb1[4], kb2[4];
                ldsm4(kb0, off0);
                ldsm4(kb1, off0 + KPLANE);
                ldsm4(kb2, off0 + 2*KPLANE);
#pragma unroll
                for (int nj = 0; nj < 2; nj++) {
                    float* s = sf[i*2 + nj];
                    const uint32_t* f0 = &kb0[nj*2];
                    const uint32_t* f1 = &kb1[nj*2];
                    const uint32_t* f2 = &kb2[nj*2];
                    mma16816(s, qf[0][ks], f0);
                    mma16816(s, qf[0][ks], f1);
                    mma16816(s, qf[1][ks], f0);
                    mma16816(s, qf[0][ks], f2);
                    mma16816(s, qf[1][ks], f1);
                    mma16816(s, qf[2][ks], f0);
                    mma16816(s, qf[1][ks], f2);
                    mma16816(s, qf[2][ks], f1);
                }
            }
        }

        // ---- tail masking (exact FMIN -> p becomes exactly 0) ----
        if (k0 + 64 > n) {
            int cb = 2*(lane & 3);
#pragma unroll
            for (int j = 0; j < 8; j++) {
                int c = k0 + 8*j + cb;
                if (c >= n)     { sf[j][0] = FMIN_F; sf[j][2] = FMIN_F; }
                if (c + 1 >= n) { sf[j][1] = FMIN_F; sf[j][3] = FMIN_F; }
            }
        }

        // ---- online softmax on fragments ----
#pragma unroll
        for (int rh = 0; rh < 2; rh++) {
            float tm = -INFINITY;
#pragma unroll
            for (int j = 0; j < 8; j++)
                tm = fmaxf(tm, fmaxf(sf[j][rh*2], sf[j][rh*2+1]));
            tm = fmaxf(tm, __shfl_xor_sync(0xFFFFFFFFu, tm, 1));
            tm = fmaxf(tm, __shfl_xor_sync(0xFFFFFFFFu, tm, 2));
            float nm = fmaxf(mx[rh], tm);
            float c = __expf(mx[rh] - nm);
            mx[rh] = nm;
            float ps = 0.f;
#pragma unroll
            for (int j = 0; j < 8; j++) {
                float e0 = __expf(sf[j][rh*2]   - nm);
                float e1 = __expf(sf[j][rh*2+1] - nm);
                sf[j][rh*2] = e0; sf[j][rh*2+1] = e1;
                ps += e0 + e1;
            }
            ls[rh] = ls[rh]*c + ps;
#pragma unroll
            for (int nf = 0; nf < 4; nf++) {
                oa[nf][rh*2]   *= c;
                oa[nf][rh*2+1] *= c;
            }
        }

        // ---- O += P V (P RN 3-plane, V RN 2-plane, 5 products) ----
#pragma unroll
        for (int g = 0; g < 4; g++) {
            float* s0 = sf[2*g];
            float* s1 = sf[2*g+1];
            uint16_t t0[8], t1[8], t2[8];
#pragma unroll
            for (int u = 0; u < 4; u++) split3(s0[u], t0[u],   t1[u],   t2[u]);
#pragma unroll
            for (int u = 0; u < 4; u++) split3(s1[u], t0[4+u], t1[4+u], t2[4+u]);
            uint32_t ap0[4], ap1[4], ap2[4];
#pragma unroll
            for (int u = 0; u < 4; u++) {
                ap0[u] = pack16(t0[2*u], t0[2*u+1]);
                ap1[u] = pack16(t1[2*u], t1[2*u+1]);
                ap2[u] = pack16(t2[2*u], t2[2*u+1]);
            }
#pragma unroll
            for (int nb = 0; nb < 2; nb++) {
                uint32_t v0r[4], v1r[4];
                uint32_t voff = smem_u32(&sV[0][g*16 + (lane & 15)][nb*16 + (lane >> 4)*8]);
                ldsm4t(v0r, voff);
                ldsm4t(v1r, voff + KPLANE);
#pragma unroll
                for (int nj = 0; nj < 2; nj++) {
                    int nf = nb*2 + nj;
                    mma16816(oa[nf], ap0, &v0r[nj*2]);
                    mma16816(oa[nf], ap0, &v1r[nj*2]);
                    mma16816(oa[nf], ap1, &v0r[nj*2]);
                    mma16816(oa[nf], ap1, &v1r[nj*2]);
                    mma16816(oa[nf], ap2, &v0r[nj*2]);
                }
            }
        }
    }

    // ---- epilogue ----
    float inv[2];
#pragma unroll
    for (int rh = 0; rh < 2; rh++) {
        float l = ls[rh];
        l += __shfl_xor_sync(0xFFFFFFFFu, l, 1);
        l += __shfl_xor_sync(0xFFFFFFFFu, l, 2);
        inv[rh] = 1.f / l;
    }
    int r0 = q0 + wid*16 + (lane >> 2);
    int cb = 2*(lane & 3);
#pragma unroll
    for (int nf = 0; nf < 4; nf++)
#pragma unroll
        for (int rh = 0; rh < 2; rh++) {
            int row = r0 + rh*8;
            float2 val = make_float2(oa[nf][rh*2]*inv[rh], oa[nf][rh*2+1]*inv[rh]);
            *(float2*)(g_o + (size_t)(b*SL + row)*DD + h*32 + 8*nf + cb) = val;
        }
}

// ---------------- fusion attention logits ------------------------------------
__global__ void fuse_att_kernel(const float* __restrict__ Wf, const float* __restrict__ bf,
                                const float* __restrict__ uf)
{
    int tok = blockIdx.x;
    int b = tok >> 11, j = tok & 2047;
    if (j >= g_nb[b]) return;
    int d = threadIdx.x;
    __shared__ float xs[DD];
    __shared__ float red[128];
    xs[d] = g_x[(size_t)tok*DD + d];
    __syncthreads();
    float acc = bf[d];
#pragma unroll 8
    for (int k = 0; k < DD; k++) acc += xs[k]*Wf[k*DD + d];
    red[d] = tanhf(acc)*uf[d];
    __syncthreads();
    for (int s = 64; s > 0; s >>= 1) {
        if (d < s) red[d] += red[d + s];
        __syncthreads();
    }
    if (d == 0) g_att[tok] = red[0];
}

// ---------------- masked softmax pooling -------------------------------------
__global__ void pool_kernel()
{
    int b = blockIdx.x;
    int n = g_nb[b];
    int tid = threadIdx.x;
    __shared__ float w[SL];
    __shared__ float red[256];
    float mx = -INFINITY;
    for (int l = tid; l < n; l += 256) mx = fmaxf(mx, g_att[b*SL + l]);
    red[tid] = mx; __syncthreads();
    for (int s = 128; s > 0; s >>= 1) { if (tid < s) red[tid] = fmaxf(red[tid], red[tid+s]); __syncthreads(); }
    mx = red[0]; __syncthreads();
    float sum = 0.f;
    for (int l = tid; l < n; l += 256) { float e = __expf(g_att[b*SL+l] - mx); w[l] = e; sum += e; }
    red[tid] = sum; __syncthreads();
    for (int s = 128; s > 0; s >>= 1) { if (tid < s) red[tid] += red[tid+s]; __syncthreads(); }
    float inv = 1.f / red[0];
    __syncthreads();
    int d = tid & 127, half = tid >> 7;
    float acc = 0.f;
    for (int l = half; l < n; l += 2)
        acc += w[l]*g_x[((size_t)b*SL + l)*DD + d];
    red[tid] = acc; __syncthreads();
    if (tid < 128) g_ts[b*DD + tid] = (red[tid] + red[tid+128])*inv;
}

// ---------------- demographics MLP -------------------------------------------
__global__ void demo_kernel(const float* __restrict__ demo, const float* __restrict__ Wd1,
                            const float* __restrict__ bd1, const float* __restrict__ Wd2,
                            const float* __restrict__ bd2)
{
    int b = blockIdx.x;
    int tid = threadIdx.x;
    __shared__ float ds[DMG];
    __shared__ float hs[256];
    if (tid < DMG) ds[tid] = demo[b*DMG + tid];
    __syncthreads();
    float a = bd1[tid];
#pragma unroll
    for (int k = 0; k < DMG; k++) a += ds[k]*Wd1[k*256 + tid];
    hs[tid] = tanhf(a);
    __syncthreads();
    if (tid < DD) {
        float a2 = bd2[tid];
#pragma unroll 8
        for (int k = 0; k < 256; k++) a2 += hs[k]*Wd2[k*DD + tid];
        g_demo[b*DD + tid] = a2;
    }
}

// ---------------- head --------------------------------------------------------
__global__ void head_kernel(const float* __restrict__ Wh, const float* __restrict__ bh,
                            float* __restrict__ out)
{
    int b = blockIdx.x;
    int tid = threadIdx.x;
    __shared__ float es[256];
    es[tid] = (tid < 128) ? g_ts[b*DD + tid] : g_demo[b*DD + (tid - 128)];
    __syncthreads();
    if (tid < NF) {
        float acc = bh[tid];
#pragma unroll 8
        for (int k = 0; k < 256; k++) acc += es[k]*Wh[k*NF + tid];
        out[b*NF + tid] = acc;
    }
}

// ---------------- orchestration ------------------------------------------------
extern "C" void kernel_launch(void* const* d_in, const int* in_sizes, int n_in,
                              void* d_out, int out_size)
{
    const float* values = (const float*)d_in[0];
    const float* times  = (const float*)d_in[1];
    const int*   vars   = (const int*)d_in[2];
    const void*  maskraw = d_in[3];
    const float* demo   = (const float*)d_in[4];
    const float* W1t = (const float*)d_in[5];
    const float* b1t = (const float*)d_in[6];
    const float* W2t = (const float*)d_in[7];
    const float* W1v = (const float*)d_in[8];
    const float* b1v = (const float*)d_in[9];
    const float* W2v = (const float*)d_in[10];
    const float* vtab = (const float*)d_in[11];
    const float* Wq = (const float*)d_in[12];
    const float* Wk = (const float*)d_in[13];
    const float* Wv = (const float*)d_in[14];
    const float* Wo = (const float*)d_in[15];
    const float* W1 = (const float*)d_in[16];
    const float* b1 = (const float*)d_in[17];
    const float* W2 = (const float*)d_in[18];
    const float* b2 = (const float*)d_in[19];
    const float* Wf = (const float*)d_in[20];
    const float* bf = (const float*)d_in[21];
    const float* uf = (const float*)d_in[22];
    const float* Wd1 = (const float*)d_in[23];
    const float* bd1 = (const float*)d_in[24];
    const float* Wd2 = (const float*)d_in[25];
    const float* bd2 = (const float*)d_in[26];
    const float* Wh = (const float*)d_in[27];
    const float* bh = (const float*)d_in[28];
    float* out = (float*)d_out;

    float *xp, *qkvp, *op, *ffp;
    __nv_bfloat16 *w0p, *w1p, *w2p;
    cudaGetSymbolAddress((void**)&xp,   g_x);
    cudaGetSymbolAddress((void**)&qkvp, g_qkv);
    cudaGetSymbolAddress((void**)&op,   g_o);
    cudaGetSymbolAddress((void**)&ffp,  g_ff);
    cudaGetSymbolAddress((void**)&w0p,  g_wt0);
    cudaGetSymbolAddress((void**)&w1p,  g_wt1);
    cudaGetSymbolAddress((void**)&w2p,  g_wt2);

    cudaFuncSetAttribute(tgemm_kernel, cudaFuncAttributeMaxDynamicSharedMemorySize, TG_SMEM);

    mask_reset_kernel<<<1, 32>>>();
    mask_scan_kernel<<<NTOK/4/256, 256>>>((const unsigned int*)maskraw);
    mask_convert_kernel<<<NTOK/256, 256>>>(maskraw);
    compact_kernel<<<BB, 256>>>();

    wrepack_kernel<<<NLAY*WT_LAYER/256, 256>>>(Wq, Wk, Wv, Wo, W1, W2);
    demo_kernel<<<BB, 256>>>(demo, Wd1, bd1, Wd2, bd2);
    embed_kernel<<<NTOK, 128>>>(values, times, vars, W1t, b1t, W2t, W1v, b1v, W2v, vtab);

    for (int i = 0; i < NLAY; i++) {
        const __nv_bfloat16* l0 = w0p + i*WT_LAYER;
        const __nv_bfloat16* l1 = w1p + i*WT_LAYER;
        const __nv_bfloat16* l2 = w2p + i*WT_LAYER;
        tgemm_kernel<<<dim3(3, NTOK/128), 256, TG_SMEM>>>(xp, l0 + WT_QKV, l1 + WT_QKV, l2 + WT_QKV,
                                                          nullptr, qkvp, 384, 128, 0);
        qkvsplit_kernel<<<NTOK*32/256, 256>>>();
        flash_kernel<<<dim3(SL/64, BB*HH), 128>>>();
        tgemm_kernel<<<dim3(1, NTOK/128), 256, TG_SMEM>>>(op, l0 + WT_WO, l1 + WT_WO, l2 + WT_WO,
                                                          nullptr, xp, 128, 128, 1);
        tgemm_kernel<<<dim3(2, NTOK/128), 256, TG_SMEM>>>(xp, l0 + WT_W1, l1 + WT_W1, l2 + WT_W1,
                                                          b1 + i*DFF, ffp, 256, 128, 2);
        tgemm_kernel<<<dim3(1, NTOK/128), 256, TG_SMEM>>>(ffp, l0 + WT_W2, l1 + WT_W2, l2 + WT_W2,
                                                          b2 + i*DD, xp, 128, 256, 3);
    }

    fuse_att_kernel<<<NTOK, 128>>>(Wf, bf, uf);
    pool_kernel<<<BB, 256>>>();
    head_kernel<<<BB, 256>>>(Wh, bh, out);
}

// round 11
// speedup vs baseline: 4.5895x; 1.0894x over previous
#include <cuda_runtime.h>
#include <cuda_bf16.h>
#include <math.h>
#include <stdint.h>

#define BB   16
#define SL   2048
#define DD   128
#define HH   4
#define NLAY 4
#define DKH  32
#define DFF  256
#define NF   129
#define DMG  16
#define INTD 11
#define NTOK (BB*SL)
#define FMIN_F (-3.402823466e38f)

// per-layer transposed bf16 weight planes: qkv[384x128] | wo[128x128] | w1[256x128] | w2[128x256]
#define WT_LAYER 131072
#define WT_QKV   0
#define WT_WO    49152
#define WT_W1    65536
#define WT_W2    98304
#define WF_OFF   (NLAY*WT_LAYER)          // Wf plane appended after layer weights
#define WT_TOTAL (WF_OFF + DD*DD)

// ---------------- scratch (device globals: allocation-free) ----------------
__device__ float g_x[NTOK*DD];
__device__ float g_qkv[NTOK*3*DD];
__device__ float g_o[NTOK*DD];
__device__ float g_ff[NTOK*DFF];
__device__ float g_demo[BB*DD];
__device__ float g_att[BB*SL];
__device__ float g_ts[BB*DD];
__device__ __nv_bfloat16 g_wt0[WT_TOTAL];
__device__ __nv_bfloat16 g_wt1[WT_TOTAL];
__device__ __nv_bfloat16 g_wt2[WT_TOTAL];
// per-(b,h) split planes of K (3) and V (2): [((b*4+h)*SL + j)*32 + e]
#define PL_ELEMS (BB*HH*SL*DKH)
__device__ __nv_bfloat16 g_k0[PL_ELEMS];
__device__ __nv_bfloat16 g_k1[PL_ELEMS];
__device__ __nv_bfloat16 g_k2[PL_ELEMS];
__device__ __nv_bfloat16 g_v0[PL_ELEMS];
__device__ __nv_bfloat16 g_v1[PL_ELEMS];
__device__ unsigned char g_mask[NTOK];
__device__ int g_idx[NTOK];
__device__ int g_nb[BB];
__device__ int g_npad[BB];
__device__ int g_cnt[2];

// ---------------- PTX helpers -------------------------------------------------
__device__ __forceinline__ uint32_t smem_u32(const void* p) {
    uint32_t a;
    asm("{ .reg .u64 t; cvta.to.shared.u64 t, %1; cvt.u32.u64 %0, t; }" : "=r"(a) : "l"(p));
    return a;
}
__device__ __forceinline__ void ldsm4(uint32_t* r, uint32_t addr) {
    asm volatile("ldmatrix.sync.aligned.m8n8.x4.shared.b16 {%0,%1,%2,%3}, [%4];"
        : "=r"(r[0]), "=r"(r[1]), "=r"(r[2]), "=r"(r[3]) : "r"(addr));
}
__device__ __forceinline__ void ldsm4t(uint32_t* r, uint32_t addr) {
    asm volatile("ldmatrix.sync.aligned.m8n8.x4.trans.shared.b16 {%0,%1,%2,%3}, [%4];"
        : "=r"(r[0]), "=r"(r[1]), "=r"(r[2]), "=r"(r[3]) : "r"(addr));
}
__device__ __forceinline__ void mma16816(float* d, const uint32_t* a, const uint32_t* b) {
    asm volatile("mma.sync.aligned.m16n8k16.row.col.f32.bf16.bf16.f32 "
        "{%0,%1,%2,%3}, {%4,%5,%6,%7}, {%8,%9}, {%0,%1,%2,%3};"
        : "+f"(d[0]), "+f"(d[1]), "+f"(d[2]), "+f"(d[3])
        : "r"(a[0]), "r"(a[1]), "r"(a[2]), "r"(a[3]), "r"(b[0]), "r"(b[1]));
}
// RN 3-way split (weights, Q, K, P)
__device__ __forceinline__ void split3(float x, uint16_t& h0, uint16_t& h1, uint16_t& h2) {
    __nv_bfloat16 b0 = __float2bfloat16(x);
    float r1 = x - __bfloat162float(b0);
    __nv_bfloat16 b1 = __float2bfloat16(r1);
    float r2 = r1 - __bfloat162float(b1);
    __nv_bfloat16 b2 = __float2bfloat16(r2);
    h0 = __bfloat16_as_ushort(b0);
    h1 = __bfloat16_as_ushort(b1);
    h2 = __bfloat16_as_ushort(b2);
}
// RN 2-way split (V)
__device__ __forceinline__ void split2(float x, uint16_t& h0, uint16_t& h1) {
    __nv_bfloat16 b0 = __float2bfloat16(x);
    float r1 = x - __bfloat162float(b0);
    __nv_bfloat16 b1 = __float2bfloat16(r1);
    h0 = __bfloat16_as_ushort(b0);
    h1 = __bfloat16_as_ushort(b1);
}
__device__ __forceinline__ uint32_t pack16(uint16_t lo, uint16_t hi) {
    return (uint32_t)lo | ((uint32_t)hi << 16);
}

// ---------------- mask dtype detection + normalization ----------------------
__global__ void mask_reset_kernel() {
    if (threadIdx.x < 2) g_cnt[threadIdx.x] = 0;
}
__global__ void mask_scan_kernel(const unsigned int* __restrict__ w) {
    int i = blockIdx.x*256 + threadIdx.x;
    unsigned int v = w[i];
    if (v > 1u) atomicOr(&g_cnt[0], 1);
    if (v != 0u && v != 0x3F800000u) atomicOr(&g_cnt[1], 1);
}
__global__ void mask_convert_kernel(const void* __restrict__ p) {
    int i = blockIdx.x*256 + threadIdx.x;
    unsigned char m;
    if (g_cnt[0] == 0)       m = (unsigned char)(((const int*)p)[i] != 0);
    else if (g_cnt[1] == 0)  m = (unsigned char)(((const float*)p)[i] != 0.0f);
    else                     m = (unsigned char)(((const unsigned char*)p)[i] != 0);
    g_mask[i] = m;
}

// ---------------- stable compaction ------------------------------------------
__global__ void compact_kernel()
{
    int b = blockIdx.x, tid = threadIdx.x;
    __shared__ int sc[256];
    __shared__ int sbase;
    if (tid == 0) sbase = 0;
    __syncthreads();
    for (int c = 0; c < SL; c += 256) {
        int l = c + tid;
        int m = g_mask[b*SL + l];
        sc[tid] = m;
        __syncthreads();
#pragma unroll
        for (int s = 1; s < 256; s <<= 1) {
            int v = (tid >= s) ? sc[tid - s] : 0;
            __syncthreads();
            sc[tid] += v;
            __syncthreads();
        }
        int pos = sbase + sc[tid] - m;
        if (m) g_idx[b*SL + pos] = l;
        int tot = sc[255];
        __syncthreads();
        if (tid == 0) sbase += tot;
        __syncthreads();
    }
    if (tid == 0) { g_nb[b] = sbase; g_npad[b] = (sbase + 127) & ~127; }
}

// ---------------- embedding (compacted) --------------------------------------
__global__ void embed_kernel(const float* __restrict__ values, const float* __restrict__ times,
                             const int* __restrict__ vars,
                             const float* __restrict__ W1t, const float* __restrict__ b1t,
                             const float* __restrict__ W2t,
                             const float* __restrict__ W1v, const float* __restrict__ b1v,
                             const float* __restrict__ W2v,
                             const float* __restrict__ vtab)
{
    int tok = blockIdx.x;
    int b = tok >> 11, j = tok & 2047;
    int d = threadIdx.x;
    if (j >= g_npad[b]) return;
    if (j >= g_nb[b]) { g_x[(size_t)tok*DD + d] = 0.f; return; }
    int l = g_idx[tok];
    __shared__ float tt[INTD], vv[INTD];
    if (d < INTD) {
        float t = times[b*SL + l], v = values[b*SL + l];
        tt[d] = tanhf(t * W1t[d] + b1t[d]);
        vv[d] = tanhf(v * W1v[d] + b1v[d]);
    }
    __syncthreads();
    int var = vars[b*SL + l];
    float acc = vtab[var*DD + d];
#pragma unroll
    for (int i = 0; i < INTD; i++)
        acc += tt[i]*W2t[i*DD+d] + vv[i]*W2v[i*DD+d];
    g_x[(size_t)tok*DD + d] = acc;
}

// ---------------- weight repack: transpose + bf16 3-way split ----------------
__global__ void wrepack_kernel(const float* __restrict__ Wq, const float* __restrict__ Wk,
                               const float* __restrict__ Wv, const float* __restrict__ Wo,
                               const float* __restrict__ W1, const float* __restrict__ W2,
                               const float* __restrict__ Wf)
{
    int idx = blockIdx.x*256 + threadIdx.x;      // < WT_TOTAL
    float v;
    if (idx >= WF_OFF) {             // fusion Wf: [dout][din] transposed
        int rr = idx - WF_OFF;
        int n = rr >> 7, k = rr & 127;
        v = Wf[k*DD + n];
    } else {
        int layer = idx >> 17;
        int r = idx & (WT_LAYER-1);
        if (r < WT_WO) {                 // qkv: n = sel*128+h*32+e, k = d
            int n = r >> 7, k = r & 127;
            int sel = n >> 7;
            int he = n & 127, h = he >> 5, e = he & 31;
            const float* W = sel == 0 ? Wq : (sel == 1 ? Wk : Wv);
            v = W[layer*HH*DD*DKH + h*DD*DKH + k*DKH + e];
        } else if (r < WT_W1) {          // wo: [dout][din]
            int rr = r - WT_WO; int n = rr >> 7, k = rr & 127;
            v = Wo[layer*DD*DD + k*DD + n];
        } else if (r < WT_W2) {          // w1: [f][d]
            int rr = r - WT_W1; int n = rr >> 7, k = rr & 127;
            v = W1[layer*DD*DFF + k*DFF + n];
        } else {                         // w2: [d][f]
            int rr = r - WT_W2; int n = rr >> 8, k = rr & 255;
            v = W2[layer*DFF*DD + k*DD + n];
        }
    }
    uint16_t h0, h1, h2;
    split3(v, h0, h1, h2);
    g_wt0[idx] = __ushort_as_bfloat16(h0);
    g_wt1[idx] = __ushort_as_bfloat16(h1);
    g_wt2[idx] = __ushort_as_bfloat16(h2);
}

// ---------------- HMMA 3-way-split GEMM: C tile 128x128 ----------------------
// epi: 0 none | 1 +=C | 2 bias+gelu | 3 bias+ +=C | 4 bias+tanh
#define PLANE 10240                        // 128 rows * 40 cols * 2B (tgemm planes)
#define TG_SMEM (6*PLANE)

__global__ __launch_bounds__(256)
void tgemm_kernel(const float* __restrict__ A,
                  const __nv_bfloat16* __restrict__ B0,
                  const __nv_bfloat16* __restrict__ B1,
                  const __nv_bfloat16* __restrict__ B2,
                  const float* __restrict__ bias,
                  float* __restrict__ C, int N, int K, int epi)
{
    int bm = blockIdx.y * 128;
    if ((bm & 2047) >= g_npad[bm >> 11]) return;
    int bn = blockIdx.x * 128;

    extern __shared__ char smem[];
    uint16_t (*sA0)[40] = (uint16_t(*)[40])(smem);
    uint16_t (*sA1)[40] = (uint16_t(*)[40])(smem + PLANE);
    uint16_t (*sA2)[40] = (uint16_t(*)[40])(smem + 2*PLANE);
    uint16_t (*sB0)[40] = (uint16_t(*)[40])(smem + 3*PLANE);
    uint16_t (*sB1)[40] = (uint16_t(*)[40])(smem + 4*PLANE);
    uint16_t (*sB2)[40] = (uint16_t(*)[40])(smem + 5*PLANE);

    int tid = threadIdx.x, wid = tid >> 5, lane = tid & 31;
    int wm = (wid & 3) * 32, wn = (wid >> 2) * 64;

    float acc[2][8][4];
#pragma unroll
    for (int mi = 0; mi < 2; mi++)
#pragma unroll
        for (int ni = 0; ni < 8; ni++)
#pragma unroll
            for (int c = 0; c < 4; c++) acc[mi][ni][c] = 0.f;

    uint32_t bA0 = smem_u32(sA0), bA1 = smem_u32(sA1), bA2 = smem_u32(sA2);
    uint32_t bB0 = smem_u32(sB0), bB1 = smem_u32(sB1), bB2 = smem_u32(sB2);
    int rowA = lane & 15, colA8 = (lane >> 4) * 8;
    int rowB = ((lane >> 4) << 3) + (lane & 7), colB8 = ((lane >> 3) & 1) * 8;

    for (int k0 = 0; k0 < K; k0 += 32) {
#pragma unroll
        for (int it = 0; it < 4; it++) {
            int idx = tid + it*256;             // 1024 float4-groups
            int row = idx >> 3, c4 = (idx & 7) * 4;
            float4 a = *(const float4*)(A + (size_t)(bm + row)*K + k0 + c4);
            float av[4] = {a.x, a.y, a.z, a.w};
            uint16_t p0[4], p1[4], p2[4];
#pragma unroll
            for (int u = 0; u < 4; u++) split3(av[u], p0[u], p1[u], p2[u]);
            *(uint2*)&sA0[row][c4] = *(uint2*)p0;
            *(uint2*)&sA1[row][c4] = *(uint2*)p1;
            *(uint2*)&sA2[row][c4] = *(uint2*)p2;
        }
#pragma unroll
        for (int it = 0; it < 4; it++) {
            int idx = tid + it*256;
            int row = idx >> 3, c4 = (idx & 7) * 4;
            size_t goff = (size_t)(bn + row)*K + k0 + c4;
            *(uint2*)&sB0[row][c4] = *(const uint2*)(B0 + goff);
            *(uint2*)&sB1[row][c4] = *(const uint2*)(B1 + goff);
            *(uint2*)&sB2[row][c4] = *(const uint2*)(B2 + goff);
        }
        __syncthreads();

#pragma unroll
        for (int ks = 0; ks < 32; ks += 16) {
            uint32_t a0[2][4], a1[2][4], a2[2][4];
#pragma unroll
            for (int mi = 0; mi < 2; mi++) {
                uint32_t off = ((uint32_t)((wm + mi*16 + rowA)*40 + ks + colA8)) * 2;
                ldsm4(a0[mi], bA0 + off);
                ldsm4(a1[mi], bA1 + off);
                ldsm4(a2[mi], bA2 + off);
            }
#pragma unroll
            for (int pi = 0; pi < 4; pi++) {
                uint32_t off = ((uint32_t)((wn + pi*16 + rowB)*40 + ks + colB8)) * 2;
                uint32_t b0[4], b1[4], b2[4];
                ldsm4(b0, bB0 + off);
                ldsm4(b1, bB1 + off);
                ldsm4(b2, bB2 + off);
#pragma unroll
                for (int mi = 0; mi < 2; mi++)
#pragma unroll
                    for (int nj = 0; nj < 2; nj++) {
                        float* ac = acc[mi][pi*2 + nj];
                        const uint32_t* f0 = &b0[nj*2];
                        const uint32_t* f1 = &b1[nj*2];
                        const uint32_t* f2 = &b2[nj*2];
                        mma16816(ac, a0[mi], f0);
                        mma16816(ac, a0[mi], f1);
                        mma16816(ac, a1[mi], f0);
                        mma16816(ac, a0[mi], f2);
                        mma16816(ac, a1[mi], f1);
                        mma16816(ac, a2[mi], f0);
                    }
            }
        }
        __syncthreads();
    }

    int r0base = bm + wm + (lane >> 2);
    int cbase = wn + (lane & 3) * 2;
#pragma unroll
    for (int mi = 0; mi < 2; mi++) {
#pragma unroll
        for (int ni = 0; ni < 8; ni++) {
            int col = bn + cbase + ni*8;
#pragma unroll
            for (int half = 0; half < 2; half++) {
                int row = r0base + mi*16 + half*8;
                float v0 = acc[mi][ni][half*2], v1 = acc[mi][ni][half*2+1];
                float* Cp = C + (size_t)row*N + col;
                if (epi >= 2) {
                    v0 += bias[col]; v1 += bias[col+1];
                }
                if (epi == 2) {
                    v0 = 0.5f*v0*(1.f + erff(v0*0.7071067811865476f));
                    v1 = 0.5f*v1*(1.f + erff(v1*0.7071067811865476f));
                }
                if (epi == 4) {
                    v0 = tanhf(v0);
                    v1 = tanhf(v1);
                }
                if (epi == 1 || epi == 3) {
                    float2 o = *(const float2*)Cp;
                    v0 += o.x; v1 += o.y;
                }
                *(float2*)Cp = make_float2(v0, v1);
            }
        }
    }
}

// ---------------- K/V plane split (once per layer, RN splits) ----------------
__global__ void qkvsplit_kernel()
{
    int idx = blockIdx.x*256 + threadIdx.x;   // NTOK*32 threads, 8 elems each
    int tok = idx >> 5;
    int grp = idx & 31;
    int b = tok >> 11, j = tok & 2047;
    if (j >= g_npad[b]) return;
    int sel = grp >> 4;                        // 0=K, 1=V
    int h = (grp >> 2) & 3;
    int e = (grp & 3) * 8;
    const float* src = g_qkv + (size_t)tok*384 + 128 + sel*128 + h*32 + e;
    float4 f0 = *(const float4*)src;
    float4 f1 = *(const float4*)(src + 4);
    float v[8] = {f0.x, f0.y, f0.z, f0.w, f1.x, f1.y, f1.z, f1.w};
    size_t dst = ((size_t)(b*4 + h)*SL + j)*32 + e;
    if (sel == 0) {
        uint16_t p0[8], p1[8], p2[8];
#pragma unroll
        for (int u = 0; u < 8; u++) split3(v[u], p0[u], p1[u], p2[u]);
        *(uint4*)(g_k0 + dst) = *(uint4*)p0;
        *(uint4*)(g_k1 + dst) = *(uint4*)p1;
        *(uint4*)(g_k2 + dst) = *(uint4*)p2;
    } else {
        uint16_t p0[8], p1[8];
#pragma unroll
        for (int u = 0; u < 8; u++) split2(v[u], p0[u], p1[u]);
        *(uint4*)(g_v0 + dst) = *(uint4*)p0;
        *(uint4*)(g_v1 + dst) = *(uint4*)p1;
    }
}

// ---------------- HMMA flash attention ---------------------------------------
// block: 4 warps, 64 queries x one (b,h); key tiles of 64, cp.async double-buffered
#define KPLANE 5120                 // one [64][40] uint16 plane
#define FL_SQ   0
#define FL_BUF  (3*KPLANE)          // 15360
#define FL_BUFSZ (5*KPLANE)         // K0 K1 K2 V0 V1 = 25600
#define FL_SMEM (FL_BUF + 2*FL_BUFSZ)  // 66560

__device__ __forceinline__ void stage_kv_async(uint32_t dstb, int bh, int k0, int tid)
{
#pragma unroll
    for (int it = 0; it < 10; it++) {
        int idx = tid + it*128;             // 1280 uint4
        int plane = idx >> 8;               // 0..4
        int r = (idx >> 2) & 63;
        int e8 = (idx & 3) * 8;
        const __nv_bfloat16* src =
            plane == 0 ? g_k0 : plane == 1 ? g_k1 : plane == 2 ? g_k2 :
            plane == 3 ? g_v0 : g_v1;
        const void* gptr = src + ((size_t)bh*SL + k0 + r)*32 + e8;
        uint32_t dst = dstb + plane*KPLANE + r*80 + e8*2;
        asm volatile("cp.async.cg.shared.global [%0], [%1], 16;"
                     :: "r"(dst), "l"(gptr) : "memory");
    }
    asm volatile("cp.async.commit_group;" ::: "memory");
}

__global__ __launch_bounds__(128)
void flash_kernel()
{
    extern __shared__ char fsm[];
    int bh = blockIdx.y;
    int b = bh >> 2, h = bh & 3;
    int n = g_nb[b];
    int q0 = blockIdx.x * 64;
    if (q0 >= n) return;

    int tid = threadIdx.x, wid = tid >> 5, lane = tid & 31;
    uint32_t sbase = smem_u32(fsm);

    // ---- stage Q (fp32 -> RN 3-plane split) ----
#pragma unroll
    for (int it = 0; it < 4; it++) {
        int idx = tid + it*128;                 // 512 float4-groups
        int row = idx >> 3, c4 = (idx & 7) * 4;
        float4 f = *(const float4*)(g_qkv + (size_t)(b*SL + q0 + row)*384 + h*32 + c4);
        float av[4] = {f.x, f.y, f.z, f.w};
        uint16_t p0[4], p1[4], p2[4];
#pragma unroll
        for (int u = 0; u < 4; u++) split3(av[u], p0[u], p1[u], p2[u]);
        *(uint2*)(fsm + FL_SQ + 0*KPLANE + row*80 + c4*2) = *(uint2*)p0;
        *(uint2*)(fsm + FL_SQ + 1*KPLANE + row*80 + c4*2) = *(uint2*)p1;
        *(uint2*)(fsm + FL_SQ + 2*KPLANE + row*80 + c4*2) = *(uint2*)p2;
    }
    __syncthreads();

    // Q fragments held in registers for the whole kernel
    uint32_t qf[3][2][4];
    int rowA = lane & 15, colA8 = (lane >> 4) * 8;
#pragma unroll
    for (int p = 0; p < 3; p++)
#pragma unroll
        for (int ks = 0; ks < 2; ks++)
            ldsm4(qf[p][ks], sbase + FL_SQ + p*KPLANE + (wid*16 + rowA)*80 + (ks*16 + colA8)*2);

    float mx[2] = {-INFINITY, -INFINITY};
    float ls[2] = {0.f, 0.f};
    float oa[4][4];
#pragma unroll
    for (int i = 0; i < 4; i++)
#pragma unroll
        for (int u = 0; u < 4; u++) oa[i][u] = 0.f;

    int rowB = ((lane >> 4) << 3) + (lane & 7), colB8 = ((lane >> 3) & 1) * 8;

    int nt = (n + 63) >> 6;
    uint32_t bufb[2] = { sbase + FL_BUF, sbase + FL_BUF + FL_BUFSZ };
    stage_kv_async(bufb[0], bh, 0, tid);
    int cur = 0;

    for (int t = 0; t < nt; t++) {
        int k0 = t*64;
        asm volatile("cp.async.wait_group 0;" ::: "memory");
        __syncthreads();
        if (t + 1 < nt) stage_kv_async(bufb[cur ^ 1], bh, k0 + 64, tid);
        uint32_t kb = bufb[cur];
        uint32_t vb = bufb[cur] + 3*KPLANE;

        // ---- S = Q K^T (6-product RN split) ----
        float sf[8][4];
#pragma unroll
        for (int j = 0; j < 8; j++)
#pragma unroll
            for (int u = 0; u < 4; u++) sf[j][u] = 0.f;

#pragma unroll
        for (int ks = 0; ks < 2; ks++) {
#pragma unroll
            for (int i = 0; i < 4; i++) {       // n16 key groups
                uint32_t off0 = kb + (i*16 + rowB)*80 + (ks*16 + colB8)*2;
                uint32_t kb0[4], kb1[4], kb2[4];
                ldsm4(kb0, off0);
                ldsm4(kb1, off0 + KPLANE);
                ldsm4(kb2, off0 + 2*KPLANE);
#pragma unroll
                for (int nj = 0; nj < 2; nj++) {
                    float* s = sf[i*2 + nj];
                    const uint32_t* f0 = &kb0[nj*2];
                    const uint32_t* f1 = &kb1[nj*2];
                    const uint32_t* f2 = &kb2[nj*2];
                    mma16816(s, qf[0][ks], f0);
                    mma16816(s, qf[0][ks], f1);
                    mma16816(s, qf[1][ks], f0);
                    mma16816(s, qf[0][ks], f2);
                    mma16816(s, qf[1][ks], f1);
                    mma16816(s, qf[2][ks], f0);
                }
            }
        }

        // ---- tail masking (exact FMIN -> p becomes exactly 0) ----
        if (k0 + 64 > n) {
            int cb = 2*(lane & 3);
#pragma unroll
            for (int j = 0; j < 8; j++) {
                int c = k0 + 8*j + cb;
                if (c >= n)     { sf[j][0] = FMIN_F; sf[j][2] = FMIN_F; }
                if (c + 1 >= n) { sf[j][1] = FMIN_F; sf[j][3] = FMIN_F; }
            }
        }

        // ---- online softmax on fragments ----
#pragma unroll
        for (int rh = 0; rh < 2; rh++) {
            float tm = -INFINITY;
#pragma unroll
            for (int j = 0; j < 8; j++)
                tm = fmaxf(tm, fmaxf(sf[j][rh*2], sf[j][rh*2+1]));
            tm = fmaxf(tm, __shfl_xor_sync(0xFFFFFFFFu, tm, 1));
            tm = fmaxf(tm, __shfl_xor_sync(0xFFFFFFFFu, tm, 2));
            float nm = fmaxf(mx[rh], tm);
            float c = __expf(mx[rh] - nm);
            mx[rh] = nm;
            float ps = 0.f;
#pragma unroll
            for (int j = 0; j < 8; j++) {
                float e0 = __expf(sf[j][rh*2]   - nm);
                float e1 = __expf(sf[j][rh*2+1] - nm);
                sf[j][rh*2] = e0; sf[j][rh*2+1] = e1;
                ps += e0 + e1;
            }
            ls[rh] = ls[rh]*c + ps;
#pragma unroll
            for (int nf = 0; nf < 4; nf++) {
                oa[nf][rh*2]   *= c;
                oa[nf][rh*2+1] *= c;
            }
        }

        // ---- O += P V (P RN 3-plane, V RN 2-plane, 5 products) ----
#pragma unroll
        for (int g = 0; g < 4; g++) {
            float* s0 = sf[2*g];
            float* s1 = sf[2*g+1];
            uint16_t t0[8], t1[8], t2[8];
#pragma unroll
            for (int u = 0; u < 4; u++) split3(s0[u], t0[u],   t1[u],   t2[u]);
#pragma unroll
            for (int u = 0; u < 4; u++) split3(s1[u], t0[4+u], t1[4+u], t2[4+u]);
            uint32_t ap0[4], ap1[4], ap2[4];
#pragma unroll
            for (int u = 0; u < 4; u++) {
                ap0[u] = pack16(t0[2*u], t0[2*u+1]);
                ap1[u] = pack16(t1[2*u], t1[2*u+1]);
                ap2[u] = pack16(t2[2*u], t2[2*u+1]);
            }
#pragma unroll
            for (int nb = 0; nb < 2; nb++) {
                uint32_t v0r[4], v1r[4];
                uint32_t voff = vb + (g*16 + (lane & 15))*80 + (nb*16 + (lane >> 4)*8)*2;
                ldsm4t(v0r, voff);
                ldsm4t(v1r, voff + KPLANE);
#pragma unroll
                for (int nj = 0; nj < 2; nj++) {
                    int nf = nb*2 + nj;
                    mma16816(oa[nf], ap0, &v0r[nj*2]);
                    mma16816(oa[nf], ap0, &v1r[nj*2]);
                    mma16816(oa[nf], ap1, &v0r[nj*2]);
                    mma16816(oa[nf], ap1, &v1r[nj*2]);
                    mma16816(oa[nf], ap2, &v0r[nj*2]);
                }
            }
        }
        cur ^= 1;
    }

    // ---- epilogue ----
    float inv[2];
#pragma unroll
    for (int rh = 0; rh < 2; rh++) {
        float l = ls[rh];
        l += __shfl_xor_sync(0xFFFFFFFFu, l, 1);
        l += __shfl_xor_sync(0xFFFFFFFFu, l, 2);
        inv[rh] = 1.f / l;
    }
    int r0 = q0 + wid*16 + (lane >> 2);
    int cb = 2*(lane & 3);
#pragma unroll
    for (int nf = 0; nf < 4; nf++)
#pragma unroll
        for (int rh = 0; rh < 2; rh++) {
            int row = r0 + rh*8;
            float2 val = make_float2(oa[nf][rh*2]*inv[rh], oa[nf][rh*2+1]*inv[rh]);
            *(float2*)(g_o + (size_t)(b*SL + row)*DD + h*32 + 8*nf + cb) = val;
        }
}

// ---------------- fusion reduce: att[tok] = tanh(xWf+bf) . uf ----------------
// (tanh part computed by tgemm epi=4 into g_ff, N=128)
__global__ void fuse_reduce_kernel(const float* __restrict__ uf)
{
    int wid = threadIdx.x >> 5, lane = threadIdx.x & 31;
    int tok = blockIdx.x*8 + wid;
    int b = tok >> 11, j = tok & 2047;
    if (j >= g_nb[b]) return;
    const float* f = g_ff + (size_t)tok*DD;
    float acc = 0.f;
#pragma unroll
    for (int t = 0; t < 4; t++) {
        int d = lane + t*32;
        acc += f[d] * uf[d];
    }
    acc += __shfl_xor_sync(0xFFFFFFFFu, acc, 16);
    acc += __shfl_xor_sync(0xFFFFFFFFu, acc, 8);
    acc += __shfl_xor_sync(0xFFFFFFFFu, acc, 4);
    acc += __shfl_xor_sync(0xFFFFFFFFu, acc, 2);
    acc += __shfl_xor_sync(0xFFFFFFFFu, acc, 1);
    if (lane == 0) g_att[tok] = acc;
}

// ---------------- masked softmax pooling -------------------------------------
__global__ void pool_kernel()
{
    int b = blockIdx.x;
    int n = g_nb[b];
    int tid = threadIdx.x;
    __shared__ float w[SL];
    __shared__ float red[256];
    float mx = -INFINITY;
    for (int l = tid; l < n; l += 256) mx = fmaxf(mx, g_att[b*SL + l]);
    red[tid] = mx; __syncthreads();
    for (int s = 128; s > 0; s >>= 1) { if (tid < s) red[tid] = fmaxf(red[tid], red[tid+s]); __syncthreads(); }
    mx = red[0]; __syncthreads();
    float sum = 0.f;
    for (int l = tid; l < n; l += 256) { float e = __expf(g_att[b*SL+l] - mx); w[l] = e; sum += e; }
    red[tid] = sum; __syncthreads();
    for (int s = 128; s > 0; s >>= 1) { if (tid < s) red[tid] += red[tid+s]; __syncthreads(); }
    float inv = 1.f / red[0];
    __syncthreads();
    int d = tid & 127, half = tid >> 7;
    float acc = 0.f;
    for (int l = half; l < n; l += 2)
        acc += w[l]*g_x[((size_t)b*SL + l)*DD + d];
    red[tid] = acc; __syncthreads();
    if (tid < 128) g_ts[b*DD + tid] = (red[tid] + red[tid+128])*inv;
}

// ---------------- demographics MLP -------------------------------------------
__global__ void demo_kernel(const float* __restrict__ demo, const float* __restrict__ Wd1,
                            const float* __restrict__ bd1, const float* __restrict__ Wd2,
                            const float* __restrict__ bd2)
{
    int b = blockIdx.x;
    int tid = threadIdx.x;
    __shared__ float ds[DMG];
    __shared__ float hs[256];
    if (tid < DMG) ds[tid] = demo[b*DMG + tid];
    __syncthreads();
    float a = bd1[tid];
#pragma unroll
    for (int k = 0; k < DMG; k++) a += ds[k]*Wd1[k*256 + tid];
    hs[tid] = tanhf(a);
    __syncthreads();
    if (tid < DD) {
        float a2 = bd2[tid];
#pragma unroll 8
        for (int k = 0; k < 256; k++) a2 += hs[k]*Wd2[k*DD + tid];
        g_demo[b*DD + tid] = a2;
    }
}

// ---------------- head --------------------------------------------------------
__global__ void head_kernel(const float* __restrict__ Wh, const float* __restrict__ bh,
                            float* __restrict__ out)
{
    int b = blockIdx.x;
    int tid = threadIdx.x;
    __shared__ float es[256];
    es[tid] = (tid < 128) ? g_ts[b*DD + tid] : g_demo[b*DD + (tid - 128)];
    __syncthreads();
    if (tid < NF) {
        float acc = bh[tid];
#pragma unroll 8
        for (int k = 0; k < 256; k++) acc += es[k]*Wh[k*NF + tid];
        out[b*NF + tid] = acc;
    }
}

// ---------------- orchestration ------------------------------------------------
extern "C" void kernel_launch(void* const* d_in, const int* in_sizes, int n_in,
                              void* d_out, int out_size)
{
    const float* values = (const float*)d_in[0];
    const float* times  = (const float*)d_in[1];
    const int*   vars   = (const int*)d_in[2];
    const void*  maskraw = d_in[3];
    const float* demo   = (const float*)d_in[4];
    const float* W1t = (const float*)d_in[5];
    const float* b1t = (const float*)d_in[6];
    const float* W2t = (const float*)d_in[7];
    const float* W1v = (const float*)d_in[8];
    const float* b1v = (const float*)d_in[9];
    const float* W2v = (const float*)d_in[10];
    const float* vtab = (const float*)d_in[11];
    const float* Wq = (const float*)d_in[12];
    const float* Wk = (const float*)d_in[13];
    const float* Wv = (const float*)d_in[14];
    const float* Wo = (const float*)d_in[15];
    const float* W1 = (const float*)d_in[16];
    const float* b1 = (const float*)d_in[17];
    const float* W2 = (const float*)d_in[18];
    const float* b2 = (const float*)d_in[19];
    const float* Wf = (const float*)d_in[20];
    const float* bf = (const float*)d_in[21];
    const float* uf = (const float*)d_in[22];
    const float* Wd1 = (const float*)d_in[23];
    const float* bd1 = (const float*)d_in[24];
    const float* Wd2 = (const float*)d_in[25];
    const float* bd2 = (const float*)d_in[26];
    const float* Wh = (const float*)d_in[27];
    const float* bh = (const float*)d_in[28];
    float* out = (float*)d_out;

    float *xp, *qkvp, *op, *ffp;
    __nv_bfloat16 *w0p, *w1p, *w2p;
    cudaGetSymbolAddress((void**)&xp,   g_x);
    cudaGetSymbolAddress((void**)&qkvp, g_qkv);
    cudaGetSymbolAddress((void**)&op,   g_o);
    cudaGetSymbolAddress((void**)&ffp,  g_ff);
    cudaGetSymbolAddress((void**)&w0p,  g_wt0);
    cudaGetSymbolAddress((void**)&w1p,  g_wt1);
    cudaGetSymbolAddress((void**)&w2p,  g_wt2);

    cudaFuncSetAttribute(tgemm_kernel, cudaFuncAttributeMaxDynamicSharedMemorySize, TG_SMEM);
    cudaFuncSetAttribute(flash_kernel, cudaFuncAttributeMaxDynamicSharedMemorySize, FL_SMEM);

    mask_reset_kernel<<<1, 32>>>();
    mask_scan_kernel<<<NTOK/4/256, 256>>>((const unsigned int*)maskraw);
    mask_convert_kernel<<<NTOK/256, 256>>>(maskraw);
    compact_kernel<<<BB, 256>>>();

    wrepack_kernel<<<WT_TOTAL/256, 256>>>(Wq, Wk, Wv, Wo, W1, W2, Wf);
    demo_kernel<<<BB, 256>>>(demo, Wd1, bd1, Wd2, bd2);
    embed_kernel<<<NTOK, 128>>>(values, times, vars, W1t, b1t, W2t, W1v, b1v, W2v, vtab);

    for (int i = 0; i < NLAY; i++) {
        const __nv_bfloat16* l0 = w0p + i*WT_LAYER;
        const __nv_bfloat16* l1 = w1p + i*WT_LAYER;
        const __nv_bfloat16* l2 = w2p + i*WT_LAYER;
        tgemm_kernel<<<dim3(3, NTOK/128), 256, TG_SMEM>>>(xp, l0 + WT_QKV, l1 + WT_QKV, l2 + WT_QKV,
                                                          nullptr, qkvp, 384, 128, 0);
        qkvsplit_kernel<<<NTOK*32/256, 256>>>();
        flash_kernel<<<dim3(SL/64, BB*HH), 128, FL_SMEM>>>();
        tgemm_kernel<<<dim3(1, NTOK/128), 256, TG_SMEM>>>(op, l0 + WT_WO, l1 + WT_WO, l2 + WT_WO,
                                                          nullptr, xp, 128, 128, 1);
        tgemm_kernel<<<dim3(2, NTOK/128), 256, TG_SMEM>>>(xp, l0 + WT_W1, l1 + WT_W1, l2 + WT_W1,
                                                          b1 + i*DFF, ffp, 256, 128, 2);
        tgemm_kernel<<<dim3(1, NTOK/128), 256, TG_SMEM>>>(ffp, l0 + WT_W2, l1 + WT_W2, l2 + WT_W2,
                                                          b2 + i*DD, xp, 128, 256, 3);
    }

    // fusion attention: tanh(x Wf + bf) via split-GEMM, then dot with uf
    tgemm_kernel<<<dim3(1, NTOK/128), 256, TG_SMEM>>>(xp, w0p + WF_OFF, w1p + WF_OFF, w2p + WF_OFF,
                                                      bf, ffp, 128, 128, 4);
    fuse_reduce_kernel<<<NTOK/8, 256>>>(uf);
    pool_kernel<<<BB, 256>>>();
    head_kernel<<<BB, 256>>>(Wh, bh, out);
}

// round 12
// speedup vs baseline: 4.7648x; 1.0382x over previous
#include <cuda_runtime.h>
#include <cuda_bf16.h>
#include <math.h>
#include <stdint.h>

#define BB   16
#define SL   2048
#define DD   128
#define HH   4
#define NLAY 4
#define DKH  32
#define DFF  256
#define NF   129
#define DMG  16
#define INTD 11
#define NTOK (BB*SL)
#define FMIN_F (-3.402823466e38f)

// per-layer transposed bf16 weight planes: qkv[384x128] | wo[128x128] | w1[256x128] | w2[128x256]
#define WT_LAYER 131072
#define WT_QKV   0
#define WT_WO    49152
#define WT_W1    65536
#define WT_W2    98304
#define WF_OFF   (NLAY*WT_LAYER)          // Wf plane appended after layer weights
#define WT_TOTAL (WF_OFF + DD*DD)

// ---------------- scratch (device globals: allocation-free) ----------------
__device__ float g_x[NTOK*DD];
__device__ float g_qkv[NTOK*3*DD];
__device__ float g_o[NTOK*DD];
__device__ float g_ff[NTOK*DFF];
__device__ float g_demo[BB*DD];
__device__ float g_att[BB*SL];
__device__ float g_ts[BB*DD];
__device__ __nv_bfloat16 g_wt0[WT_TOTAL];
__device__ __nv_bfloat16 g_wt1[WT_TOTAL];
__device__ __nv_bfloat16 g_wt2[WT_TOTAL];
// per-(b,h) split planes of K (3) and V (2): [((b*4+h)*SL + j)*32 + e]
#define PL_ELEMS (BB*HH*SL*DKH)
__device__ __nv_bfloat16 g_k0[PL_ELEMS];
__device__ __nv_bfloat16 g_k1[PL_ELEMS];
__device__ __nv_bfloat16 g_k2[PL_ELEMS];
__device__ __nv_bfloat16 g_v0[PL_ELEMS];
__device__ __nv_bfloat16 g_v1[PL_ELEMS];
__device__ unsigned char g_mask[NTOK];
__device__ int g_idx[NTOK];
__device__ int g_nb[BB];
__device__ int g_npad[BB];
__device__ int g_cnt[2];

// ---------------- PTX helpers -------------------------------------------------
__device__ __forceinline__ uint32_t smem_u32(const void* p) {
    uint32_t a;
    asm("{ .reg .u64 t; cvta.to.shared.u64 t, %1; cvt.u32.u64 %0, t; }" : "=r"(a) : "l"(p));
    return a;
}
__device__ __forceinline__ void ldsm4(uint32_t* r, uint32_t addr) {
    asm volatile("ldmatrix.sync.aligned.m8n8.x4.shared.b16 {%0,%1,%2,%3}, [%4];"
        : "=r"(r[0]), "=r"(r[1]), "=r"(r[2]), "=r"(r[3]) : "r"(addr));
}
__device__ __forceinline__ void ldsm4t(uint32_t* r, uint32_t addr) {
    asm volatile("ldmatrix.sync.aligned.m8n8.x4.trans.shared.b16 {%0,%1,%2,%3}, [%4];"
        : "=r"(r[0]), "=r"(r[1]), "=r"(r[2]), "=r"(r[3]) : "r"(addr));
}
__device__ __forceinline__ void mma16816(float* d, const uint32_t* a, const uint32_t* b) {
    asm volatile("mma.sync.aligned.m16n8k16.row.col.f32.bf16.bf16.f32 "
        "{%0,%1,%2,%3}, {%4,%5,%6,%7}, {%8,%9}, {%0,%1,%2,%3};"
        : "+f"(d[0]), "+f"(d[1]), "+f"(d[2]), "+f"(d[3])
        : "r"(a[0]), "r"(a[1]), "r"(a[2]), "r"(a[3]), "r"(b[0]), "r"(b[1]));
}
// RN 3-way split (weights, Q, K, P)
__device__ __forceinline__ void split3(float x, uint16_t& h0, uint16_t& h1, uint16_t& h2) {
    __nv_bfloat16 b0 = __float2bfloat16(x);
    float r1 = x - __bfloat162float(b0);
    __nv_bfloat16 b1 = __float2bfloat16(r1);
    float r2 = r1 - __bfloat162float(b1);
    __nv_bfloat16 b2 = __float2bfloat16(r2);
    h0 = __bfloat16_as_ushort(b0);
    h1 = __bfloat16_as_ushort(b1);
    h2 = __bfloat16_as_ushort(b2);
}
// RN 2-way split (V)
__device__ __forceinline__ void split2(float x, uint16_t& h0, uint16_t& h1) {
    __nv_bfloat16 b0 = __float2bfloat16(x);
    float r1 = x - __bfloat162float(b0);
    __nv_bfloat16 b1 = __float2bfloat16(r1);
    h0 = __bfloat16_as_ushort(b0);
    h1 = __bfloat16_as_ushort(b1);
}
__device__ __forceinline__ uint32_t pack16(uint16_t lo, uint16_t hi) {
    return (uint32_t)lo | ((uint32_t)hi << 16);
}

// ---------------- mask dtype detection + normalization ----------------------
__global__ void mask_reset_kernel() {
    if (threadIdx.x < 2) g_cnt[threadIdx.x] = 0;
}
__global__ void mask_scan_kernel(const unsigned int* __restrict__ w) {
    int i = blockIdx.x*256 + threadIdx.x;
    unsigned int v = w[i];
    if (v > 1u) atomicOr(&g_cnt[0], 1);
    if (v != 0u && v != 0x3F800000u) atomicOr(&g_cnt[1], 1);
}
__global__ void mask_convert_kernel(const void* __restrict__ p) {
    int i = blockIdx.x*256 + threadIdx.x;
    unsigned char m;
    if (g_cnt[0] == 0)       m = (unsigned char)(((const int*)p)[i] != 0);
    else if (g_cnt[1] == 0)  m = (unsigned char)(((const float*)p)[i] != 0.0f);
    else                     m = (unsigned char)(((const unsigned char*)p)[i] != 0);
    g_mask[i] = m;
}

// ---------------- stable compaction ------------------------------------------
__global__ void compact_kernel()
{
    int b = blockIdx.x, tid = threadIdx.x;
    __shared__ int sc[256];
    __shared__ int sbase;
    if (tid == 0) sbase = 0;
    __syncthreads();
    for (int c = 0; c < SL; c += 256) {
        int l = c + tid;
        int m = g_mask[b*SL + l];
        sc[tid] = m;
        __syncthreads();
#pragma unroll
        for (int s = 1; s < 256; s <<= 1) {
            int v = (tid >= s) ? sc[tid - s] : 0;
            __syncthreads();
            sc[tid] += v;
            __syncthreads();
        }
        int pos = sbase + sc[tid] - m;
        if (m) g_idx[b*SL + pos] = l;
        int tot = sc[255];
        __syncthreads();
        if (tid == 0) sbase += tot;
        __syncthreads();
    }
    if (tid == 0) { g_nb[b] = sbase; g_npad[b] = (sbase + 127) & ~127; }
}

// ---------------- embedding (compacted) --------------------------------------
__global__ void embed_kernel(const float* __restrict__ values, const float* __restrict__ times,
                             const int* __restrict__ vars,
                             const float* __restrict__ W1t, const float* __restrict__ b1t,
                             const float* __restrict__ W2t,
                             const float* __restrict__ W1v, const float* __restrict__ b1v,
                             const float* __restrict__ W2v,
                             const float* __restrict__ vtab)
{
    int tok = blockIdx.x;
    int b = tok >> 11, j = tok & 2047;
    int d = threadIdx.x;
    if (j >= g_npad[b]) return;
    if (j >= g_nb[b]) { g_x[(size_t)tok*DD + d] = 0.f; return; }
    int l = g_idx[tok];
    __shared__ float tt[INTD], vv[INTD];
    if (d < INTD) {
        float t = times[b*SL + l], v = values[b*SL + l];
        tt[d] = tanhf(t * W1t[d] + b1t[d]);
        vv[d] = tanhf(v * W1v[d] + b1v[d]);
    }
    __syncthreads();
    int var = vars[b*SL + l];
    float acc = vtab[var*DD + d];
#pragma unroll
    for (int i = 0; i < INTD; i++)
        acc += tt[i]*W2t[i*DD+d] + vv[i]*W2v[i*DD+d];
    g_x[(size_t)tok*DD + d] = acc;
}

// ---------------- weight repack: transpose + bf16 3-way split ----------------
__global__ void wrepack_kernel(const float* __restrict__ Wq, const float* __restrict__ Wk,
                               const float* __restrict__ Wv, const float* __restrict__ Wo,
                               const float* __restrict__ W1, const float* __restrict__ W2,
                               const float* __restrict__ Wf)
{
    int idx = blockIdx.x*256 + threadIdx.x;      // < WT_TOTAL
    float v;
    if (idx >= WF_OFF) {             // fusion Wf: [dout][din] transposed
        int rr = idx - WF_OFF;
        int n = rr >> 7, k = rr & 127;
        v = Wf[k*DD + n];
    } else {
        int layer = idx >> 17;
        int r = idx & (WT_LAYER-1);
        if (r < WT_WO) {                 // qkv: n = sel*128+h*32+e, k = d
            int n = r >> 7, k = r & 127;
            int sel = n >> 7;
            int he = n & 127, h = he >> 5, e = he & 31;
            const float* W = sel == 0 ? Wq : (sel == 1 ? Wk : Wv);
            v = W[layer*HH*DD*DKH + h*DD*DKH + k*DKH + e];
        } else if (r < WT_W1) {          // wo: [dout][din]
            int rr = r - WT_WO; int n = rr >> 7, k = rr & 127;
            v = Wo[layer*DD*DD + k*DD + n];
        } else if (r < WT_W2) {          // w1: [f][d]
            int rr = r - WT_W1; int n = rr >> 7, k = rr & 127;
            v = W1[layer*DD*DFF + k*DFF + n];
        } else {                         // w2: [d][f]
            int rr = r - WT_W2; int n = rr >> 8, k = rr & 255;
            v = W2[layer*DFF*DD + k*DD + n];
        }
    }
    uint16_t h0, h1, h2;
    split3(v, h0, h1, h2);
    g_wt0[idx] = __ushort_as_bfloat16(h0);
    g_wt1[idx] = __ushort_as_bfloat16(h1);
    g_wt2[idx] = __ushort_as_bfloat16(h2);
}

// ---------------- HMMA 3-way-split GEMM: C tile 128x128 ----------------------
// epi: 0 none | 1 +=C | 2 bias+gelu | 3 bias+ +=C | 4 bias+tanh | 5 qkv (q->C, k/v->split planes)
#define PLANE 10240                        // 128 rows * 40 cols * 2B (tgemm planes)
#define TG_SMEM (6*PLANE)

__global__ __launch_bounds__(256)
void tgemm_kernel(const float* __restrict__ A,
                  const __nv_bfloat16* __restrict__ B0,
                  const __nv_bfloat16* __restrict__ B1,
                  const __nv_bfloat16* __restrict__ B2,
                  const float* __restrict__ bias,
                  float* __restrict__ C, int N, int K, int epi)
{
    int bm = blockIdx.y * 128;
    if ((bm & 2047) >= g_npad[bm >> 11]) return;
    int bn = blockIdx.x * 128;

    extern __shared__ char smem[];
    uint16_t (*sA0)[40] = (uint16_t(*)[40])(smem);
    uint16_t (*sA1)[40] = (uint16_t(*)[40])(smem + PLANE);
    uint16_t (*sA2)[40] = (uint16_t(*)[40])(smem + 2*PLANE);
    uint16_t (*sB0)[40] = (uint16_t(*)[40])(smem + 3*PLANE);
    uint16_t (*sB1)[40] = (uint16_t(*)[40])(smem + 4*PLANE);
    uint16_t (*sB2)[40] = (uint16_t(*)[40])(smem + 5*PLANE);

    int tid = threadIdx.x, wid = tid >> 5, lane = tid & 31;
    int wm = (wid & 3) * 32, wn = (wid >> 2) * 64;

    float acc[2][8][4];
#pragma unroll
    for (int mi = 0; mi < 2; mi++)
#pragma unroll
        for (int ni = 0; ni < 8; ni++)
#pragma unroll
            for (int c = 0; c < 4; c++) acc[mi][ni][c] = 0.f;

    uint32_t bA0 = smem_u32(sA0), bA1 = smem_u32(sA1), bA2 = smem_u32(sA2);
    uint32_t bB0 = smem_u32(sB0), bB1 = smem_u32(sB1), bB2 = smem_u32(sB2);
    int rowA = lane & 15, colA8 = (lane >> 4) * 8;
    int rowB = ((lane >> 4) << 3) + (lane & 7), colB8 = ((lane >> 3) & 1) * 8;

    for (int k0 = 0; k0 < K; k0 += 32) {
#pragma unroll
        for (int it = 0; it < 4; it++) {
            int idx = tid + it*256;             // 1024 float4-groups
            int row = idx >> 3, c4 = (idx & 7) * 4;
            float4 a = *(const float4*)(A + (size_t)(bm + row)*K + k0 + c4);
            float av[4] = {a.x, a.y, a.z, a.w};
            uint16_t p0[4], p1[4], p2[4];
#pragma unroll
            for (int u = 0; u < 4; u++) split3(av[u], p0[u], p1[u], p2[u]);
            *(uint2*)&sA0[row][c4] = *(uint2*)p0;
            *(uint2*)&sA1[row][c4] = *(uint2*)p1;
            *(uint2*)&sA2[row][c4] = *(uint2*)p2;
        }
#pragma unroll
        for (int it = 0; it < 4; it++) {
            int idx = tid + it*256;
            int row = idx >> 3, c4 = (idx & 7) * 4;
            size_t goff = (size_t)(bn + row)*K + k0 + c4;
            *(uint2*)&sB0[row][c4] = *(const uint2*)(B0 + goff);
            *(uint2*)&sB1[row][c4] = *(const uint2*)(B1 + goff);
            *(uint2*)&sB2[row][c4] = *(const uint2*)(B2 + goff);
        }
        __syncthreads();

#pragma unroll
        for (int ks = 0; ks < 32; ks += 16) {
            uint32_t a0[2][4], a1[2][4], a2[2][4];
#pragma unroll
            for (int mi = 0; mi < 2; mi++) {
                uint32_t off = ((uint32_t)((wm + mi*16 + rowA)*40 + ks + colA8)) * 2;
                ldsm4(a0[mi], bA0 + off);
                ldsm4(a1[mi], bA1 + off);
                ldsm4(a2[mi], bA2 + off);
            }
#pragma unroll
            for (int pi = 0; pi < 4; pi++) {
                uint32_t off = ((uint32_t)((wn + pi*16 + rowB)*40 + ks + colB8)) * 2;
                uint32_t b0[4], b1[4], b2[4];
                ldsm4(b0, bB0 + off);
                ldsm4(b1, bB1 + off);
                ldsm4(b2, bB2 + off);
#pragma unroll
                for (int mi = 0; mi < 2; mi++)
#pragma unroll
                    for (int nj = 0; nj < 2; nj++) {
                        float* ac = acc[mi][pi*2 + nj];
                        const uint32_t* f0 = &b0[nj*2];
                        const uint32_t* f1 = &b1[nj*2];
                        const uint32_t* f2 = &b2[nj*2];
                        mma16816(ac, a0[mi], f0);
                        mma16816(ac, a0[mi], f1);
                        mma16816(ac, a1[mi], f0);
                        mma16816(ac, a0[mi], f2);
                        mma16816(ac, a1[mi], f1);
                        mma16816(ac, a2[mi], f0);
                    }
            }
        }
        __syncthreads();
    }

    int r0base = bm + wm + (lane >> 2);
    int cbase = wn + (lane & 3) * 2;
#pragma unroll
    for (int mi = 0; mi < 2; mi++) {
#pragma unroll
        for (int ni = 0; ni < 8; ni++) {
            int col = bn + cbase + ni*8;
#pragma unroll
            for (int half = 0; half < 2; half++) {
                int row = r0base + mi*16 + half*8;
                float v0 = acc[mi][ni][half*2], v1 = acc[mi][ni][half*2+1];
                if (epi == 5) {
                    if (col < 128) {
                        *(float2*)(C + (size_t)row*N + col) = make_float2(v0, v1);
                    } else {
                        int cc = col - 128;
                        int sel = cc >> 7;
                        int hh = (cc >> 5) & 3;
                        int e  = cc & 31;
                        int bb = row >> 11, jj = row & 2047;
                        size_t dst = ((size_t)(bb*4 + hh)*SL + jj)*32 + e;
                        if (sel == 0) {
                            uint16_t a0h, a1h, a2h, b0h, b1h, b2h;
                            split3(v0, a0h, a1h, a2h);
                            split3(v1, b0h, b1h, b2h);
                            *(uint32_t*)(g_k0 + dst) = pack16(a0h, b0h);
                            *(uint32_t*)(g_k1 + dst) = pack16(a1h, b1h);
                            *(uint32_t*)(g_k2 + dst) = pack16(a2h, b2h);
                        } else {
                            uint16_t a0h, a1h, b0h, b1h;
                            split2(v0, a0h, a1h);
                            split2(v1, b0h, b1h);
                            *(uint32_t*)(g_v0 + dst) = pack16(a0h, b0h);
                            *(uint32_t*)(g_v1 + dst) = pack16(a1h, b1h);
                        }
                    }
                    continue;
                }
                float* Cp = C + (size_t)row*N + col;
                if (epi >= 2) {
                    v0 += bias[col]; v1 += bias[col+1];
                }
                if (epi == 2) {
                    v0 = 0.5f*v0*(1.f + erff(v0*0.7071067811865476f));
                    v1 = 0.5f*v1*(1.f + erff(v1*0.7071067811865476f));
                }
                if (epi == 4) {
                    v0 = tanhf(v0);
                    v1 = tanhf(v1);
                }
                if (epi == 1 || epi == 3) {
                    float2 o = *(const float2*)Cp;
                    v0 += o.x; v1 += o.y;
                }
                *(float2*)Cp = make_float2(v0, v1);
            }
        }
    }
}

// ---------------- HMMA flash attention ---------------------------------------
// block: 8 warps, 128 queries x one (b,h); key tiles of 64, cp.async double-buffered
#define KPLANE 5120                  // one [64][40] uint16 KV plane
#define QPLANE 10240                 // one [128][40] uint16 Q plane
#define FL_SQ   0
#define FL_BUF  (3*QPLANE)           // 30720
#define FL_BUFSZ (5*KPLANE)          // K0 K1 K2 V0 V1 = 25600
#define FL_SMEM (FL_BUF + 2*FL_BUFSZ)  // 81920

__device__ __forceinline__ void stage_kv_async(uint32_t dstb, int bh, int k0, int tid)
{
#pragma unroll
    for (int it = 0; it < 5; it++) {
        int idx = tid + it*256;             // 1280 uint4
        int plane = idx >> 8;               // 0..4
        int r = (idx >> 2) & 63;
        int e8 = (idx & 3) * 8;
        const __nv_bfloat16* src =
            plane == 0 ? g_k0 : plane == 1 ? g_k1 : plane == 2 ? g_k2 :
            plane == 3 ? g_v0 : g_v1;
        const void* gptr = src + ((size_t)bh*SL + k0 + r)*32 + e8;
        uint32_t dst = dstb + plane*KPLANE + r*80 + e8*2;
        asm volatile("cp.async.cg.shared.global [%0], [%1], 16;"
                     :: "r"(dst), "l"(gptr) : "memory");
    }
    asm volatile("cp.async.commit_group;" ::: "memory");
}

__global__ __launch_bounds__(256)
void flash_kernel()
{
    extern __shared__ char fsm[];
    int bh = blockIdx.y;
    int b = bh >> 2, h = bh & 3;
    int n = g_nb[b];
    int q0 = blockIdx.x * 128;
    if (q0 >= n) return;

    int tid = threadIdx.x, wid = tid >> 5, lane = tid & 31;
    uint32_t sbase = smem_u32(fsm);

    // ---- stage Q (fp32 -> RN 3-plane split), 128 rows ----
#pragma unroll
    for (int it = 0; it < 4; it++) {
        int idx = tid + it*256;                 // 1024 float4-groups
        int row = idx >> 3, c4 = (idx & 7) * 4;
        float4 f = *(const float4*)(g_qkv + (size_t)(b*SL + q0 + row)*384 + h*32 + c4);
        float av[4] = {f.x, f.y, f.z, f.w};
        uint16_t p0[4], p1[4], p2[4];
#pragma unroll
        for (int u = 0; u < 4; u++) split3(av[u], p0[u], p1[u], p2[u]);
        *(uint2*)(fsm + FL_SQ + 0*QPLANE + row*80 + c4*2) = *(uint2*)p0;
        *(uint2*)(fsm + FL_SQ + 1*QPLANE + row*80 + c4*2) = *(uint2*)p1;
        *(uint2*)(fsm + FL_SQ + 2*QPLANE + row*80 + c4*2) = *(uint2*)p2;
    }
    __syncthreads();

    // Q fragments held in registers for the whole kernel (warp wid owns rows wid*16..+16)
    uint32_t qf[3][2][4];
    int rowA = lane & 15, colA8 = (lane >> 4) * 8;
#pragma unroll
    for (int p = 0; p < 3; p++)
#pragma unroll
        for (int ks = 0; ks < 2; ks++)
            ldsm4(qf[p][ks], sbase + FL_SQ + p*QPLANE + (wid*16 + rowA)*80 + (ks*16 + colA8)*2);

    float mx[2] = {-INFINITY, -INFINITY};
    float ls[2] = {0.f, 0.f};
    float oa[4][4];
#pragma unroll
    for (int i = 0; i < 4; i++)
#pragma unroll
        for (int u = 0; u < 4; u++) oa[i][u] = 0.f;

    int rowB = ((lane >> 4) << 3) + (lane & 7), colB8 = ((lane >> 3) & 1) * 8;

    int nt = (n + 63) >> 6;
    uint32_t bufb[2] = { sbase + FL_BUF, sbase + FL_BUF + FL_BUFSZ };
    stage_kv_async(bufb[0], bh, 0, tid);
    int cur = 0;

    for (int t = 0; t < nt; t++) {
        int k0 = t*64;
        asm volatile("cp.async.wait_group 0;" ::: "memory");
        __syncthreads();
        if (t + 1 < nt) stage_kv_async(bufb[cur ^ 1], bh, k0 + 64, tid);
        uint32_t kb = bufb[cur];
        uint32_t vb = bufb[cur] + 3*KPLANE;

        // ---- S = Q K^T (6-product RN split) ----
        float sf[8][4];
#pragma unroll
        for (int j = 0; j < 8; j++)
#pragma unroll
            for (int u = 0; u < 4; u++) sf[j][u] = 0.f;

#pragma unroll
        for (int ks = 0; ks < 2; ks++) {
#pragma unroll
            for (int i = 0; i < 4; i++) {       // n16 key groups
                uint32_t off0 = kb + (i*16 + rowB)*80 + (ks*16 + colB8)*2;
                uint32_t kb0[4], kb1[4], kb2[4];
                ldsm4(kb0, off0);
                ldsm4(kb1, off0 + KPLANE);
                ldsm4(kb2, off0 + 2*KPLANE);
#pragma unroll
                for (int nj = 0; nj < 2; nj++) {
                    float* s = sf[i*2 + nj];
                    const uint32_t* f0 = &kb0[nj*2];
                    const uint32_t* f1 = &kb1[nj*2];
                    const uint32_t* f2 = &kb2[nj*2];
                    mma16816(s, qf[0][ks], f0);
                    mma16816(s, qf[0][ks], f1);
                    mma16816(s, qf[1][ks], f0);
                    mma16816(s, qf[0][ks], f2);
                    mma16816(s, qf[1][ks], f1);
                    mma16816(s, qf[2][ks], f0);
                }
            }
        }

        // ---- tail masking (exact FMIN -> p becomes exactly 0) ----
        if (k0 + 64 > n) {
            int cb = 2*(lane & 3);
#pragma unroll
            for (int j = 0; j < 8; j++) {
                int c = k0 + 8*j + cb;
                if (c >= n)     { sf[j][0] = FMIN_F; sf[j][2] = FMIN_F; }
                if (c + 1 >= n) { sf[j][1] = FMIN_F; sf[j][3] = FMIN_F; }
            }
        }

        // ---- online softmax on fragments ----
#pragma unroll
        for (int rh = 0; rh < 2; rh++) {
            float tm = -INFINITY;
#pragma unroll
            for (int j = 0; j < 8; j++)
                tm = fmaxf(tm, fmaxf(sf[j][rh*2], sf[j][rh*2+1]));
            tm = fmaxf(tm, __shfl_xor_sync(0xFFFFFFFFu, tm, 1));
            tm = fmaxf(tm, __shfl_xor_sync(0xFFFFFFFFu, tm, 2));
            float nm = fmaxf(mx[rh], tm);
            float c = __expf(mx[rh] - nm);
            mx[rh] = nm;
            float ps = 0.f;
#pragma unroll
            for (int j = 0; j < 8; j++) {
                float e0 = __expf(sf[j][rh*2]   - nm);
                float e1 = __expf(sf[j][rh*2+1] - nm);
                sf[j][rh*2] = e0; sf[j][rh*2+1] = e1;
                ps += e0 + e1;
            }
            ls[rh] = ls[rh]*c + ps;
#pragma unroll
            for (int nf = 0; nf < 4; nf++) {
                oa[nf][rh*2]   *= c;
                oa[nf][rh*2+1] *= c;
            }
        }

        // ---- O += P V (P RN 3-plane, V RN 2-plane, 5 products) ----
#pragma unroll
        for (int g = 0; g < 4; g++) {
            float* s0 = sf[2*g];
            float* s1 = sf[2*g+1];
            uint16_t t0[8], t1[8], t2[8];
#pragma unroll
            for (int u = 0; u < 4; u++) split3(s0[u], t0[u],   t1[u],   t2[u]);
#pragma unroll
            for (int u = 0; u < 4; u++) split3(s1[u], t0[4+u], t1[4+u], t2[4+u]);
            uint32_t ap0[4], ap1[4], ap2[4];
#pragma unroll
            for (int u = 0; u < 4; u++) {
                ap0[u] = pack16(t0[2*u], t0[2*u+1]);
                ap1[u] = pack16(t1[2*u], t1[2*u+1]);
                ap2[u] = pack16(t2[2*u], t2[2*u+1]);
            }
#pragma unroll
            for (int nb = 0; nb < 2; nb++) {
                uint32_t v0r[4], v1r[4];
                uint32_t voff = vb + (g*16 + (lane & 15))*80 + (nb*16 + (lane >> 4)*8)*2;
                ldsm4t(v0r, voff);
                ldsm4t(v1r, voff + KPLANE);
#pragma unroll
                for (int nj = 0; nj < 2; nj++) {
                    int nf = nb*2 + nj;
                    mma16816(oa[nf], ap0, &v0r[nj*2]);
                    mma16816(oa[nf], ap0, &v1r[nj*2]);
                    mma16816(oa[nf], ap1, &v0r[nj*2]);
                    mma16816(oa[nf], ap1, &v1r[nj*2]);
                    mma16816(oa[nf], ap2, &v0r[nj*2]);
                }
            }
        }
        cur ^= 1;
    }

    // ---- epilogue ----
    float inv[2];
#pragma unroll
    for (int rh = 0; rh < 2; rh++) {
        float l = ls[rh];
        l += __shfl_xor_sync(0xFFFFFFFFu, l, 1);
        l += __shfl_xor_sync(0xFFFFFFFFu, l, 2);
        inv[rh] = 1.f / l;
    }
    int r0 = q0 + wid*16 + (lane >> 2);
    int cb = 2*(lane & 3);
#pragma unroll
    for (int nf = 0; nf < 4; nf++)
#pragma unroll
        for (int rh = 0; rh < 2; rh++) {
            int row = r0 + rh*8;
            float2 val = make_float2(oa[nf][rh*2]*inv[rh], oa[nf][rh*2+1]*inv[rh]);
            *(float2*)(g_o + (size_t)(b*SL + row)*DD + h*32 + 8*nf + cb) = val;
        }
}

// ---------------- fusion reduce: att[tok] = tanh(xWf+bf) . uf ----------------
// (tanh part computed by tgemm epi=4 into g_ff, N=128)
__global__ void fuse_reduce_kernel(const float* __restrict__ uf)
{
    int wid = threadIdx.x >> 5, lane = threadIdx.x & 31;
    int tok = blockIdx.x*8 + wid;
    int b = tok >> 11, j = tok & 2047;
    if (j >= g_nb[b]) return;
    const float* f = g_ff + (size_t)tok*DD;
    float acc = 0.f;
#pragma unroll
    for (int t = 0; t < 4; t++) {
        int d = lane + t*32;
        acc += f[d] * uf[d];
    }
    acc += __shfl_xor_sync(0xFFFFFFFFu, acc, 16);
    acc += __shfl_xor_sync(0xFFFFFFFFu, acc, 8);
    acc += __shfl_xor_sync(0xFFFFFFFFu, acc, 4);
    acc += __shfl_xor_sync(0xFFFFFFFFu, acc, 2);
    acc += __shfl_xor_sync(0xFFFFFFFFu, acc, 1);
    if (lane == 0) g_att[tok] = acc;
}

// ---------------- masked softmax pooling -------------------------------------
__global__ void pool_kernel()
{
    int b = blockIdx.x;
    int n = g_nb[b];
    int tid = threadIdx.x;
    __shared__ float w[SL];
    __shared__ float red[256];
    float mx = -INFINITY;
    for (int l = tid; l < n; l += 256) mx = fmaxf(mx, g_att[b*SL + l]);
    red[tid] = mx; __syncthreads();
    for (int s = 128; s > 0; s >>= 1) { if (tid < s) red[tid] = fmaxf(red[tid], red[tid+s]); __syncthreads(); }
    mx = red[0]; __syncthreads();
    float sum = 0.f;
    for (int l = tid; l < n; l += 256) { float e = __expf(g_att[b*SL+l] - mx); w[l] = e; sum += e; }
    red[tid] = sum; __syncthreads();
    for (int s = 128; s > 0; s >>= 1) { if (tid < s) red[tid] += red[tid+s]; __syncthreads(); }
    float inv = 1.f / red[0];
    __syncthreads();
    int d = tid & 127, half = tid >> 7;
    float acc = 0.f;
    for (int l = half; l < n; l += 2)
        acc += w[l]*g_x[((size_t)b*SL + l)*DD + d];
    red[tid] = acc; __syncthreads();
    if (tid < 128) g_ts[b*DD + tid] = (red[tid] + red[tid+128])*inv;
}

// ---------------- demographics MLP -------------------------------------------
__global__ void demo_kernel(const float* __restrict__ demo, const float* __restrict__ Wd1,
                            const float* __restrict__ bd1, const float* __restrict__ Wd2,
                            const float* __restrict__ bd2)
{
    int b = blockIdx.x;
    int tid = threadIdx.x;
    __shared__ float ds[DMG];
    __shared__ float hs[256];
    if (tid < DMG) ds[tid] = demo[b*DMG + tid];
    __syncthreads();
    float a = bd1[tid];
#pragma unroll
    for (int k = 0; k < DMG; k++) a += ds[k]*Wd1[k*256 + tid];
    hs[tid] = tanhf(a);
    __syncthreads();
    if (tid < DD) {
        float a2 = bd2[tid];
#pragma unroll 8
        for (int k = 0; k < 256; k++) a2 += hs[k]*Wd2[k*DD + tid];
        g_demo[b*DD + tid] = a2;
    }
}

// ---------------- head --------------------------------------------------------
__global__ void head_kernel(const float* __restrict__ Wh, const float* __restrict__ bh,
                            float* __restrict__ out)
{
    int b = blockIdx.x;
    int tid = threadIdx.x;
    __shared__ float es[256];
    es[tid] = (tid < 128) ? g_ts[b*DD + tid] : g_demo[b*DD + (tid - 128)];
    __syncthreads();
    if (tid < NF) {
        float acc = bh[tid];
#pragma unroll 8
        for (int k = 0; k < 256; k++) acc += es[k]*Wh[k*NF + tid];
        out[b*NF + tid] = acc;
    }
}

// ---------------- orchestration ------------------------------------------------
extern "C" void kernel_launch(void* const* d_in, const int* in_sizes, int n_in,
                              void* d_out, int out_size)
{
    const float* values = (const float*)d_in[0];
    const float* times  = (const float*)d_in[1];
    const int*   vars   = (const int*)d_in[2];
    const void*  maskraw = d_in[3];
    const float* demo   = (const float*)d_in[4];
    const float* W1t = (const float*)d_in[5];
    const float* b1t = (const float*)d_in[6];
    const float* W2t = (const float*)d_in[7];
    const float* W1v = (const float*)d_in[8];
    const float* b1v = (const float*)d_in[9];
    const float* W2v = (const float*)d_in[10];
    const float* vtab = (const float*)d_in[11];
    const float* Wq = (const float*)d_in[12];
    const float* Wk = (const float*)d_in[13];
    const float* Wv = (const float*)d_in[14];
    const float* Wo = (const float*)d_in[15];
    const float* W1 = (const float*)d_in[16];
    const float* b1 = (const float*)d_in[17];
    const float* W2 = (const float*)d_in[18];
    const float* b2 = (const float*)d_in[19];
    const float* Wf = (const float*)d_in[20];
    const float* bf = (const float*)d_in[21];
    const float* uf = (const float*)d_in[22];
    const float* Wd1 = (const float*)d_in[23];
    const float* bd1 = (const float*)d_in[24];
    const float* Wd2 = (const float*)d_in[25];
    const float* bd2 = (const float*)d_in[26];
    const float* Wh = (const float*)d_in[27];
    const float* bh = (const float*)d_in[28];
    float* out = (float*)d_out;

    float *xp, *qkvp, *op, *ffp;
    __nv_bfloat16 *w0p, *w1p, *w2p;
    cudaGetSymbolAddress((void**)&xp,   g_x);
    cudaGetSymbolAddress((void**)&qkvp, g_qkv);
    cudaGetSymbolAddress((void**)&op,   g_o);
    cudaGetSymbolAddress((void**)&ffp,  g_ff);
    cudaGetSymbolAddress((void**)&w0p,  g_wt0);
    cudaGetSymbolAddress((void**)&w1p,  g_wt1);
    cudaGetSymbolAddress((void**)&w2p,  g_wt2);

    cudaFuncSetAttribute(tgemm_kernel, cudaFuncAttributeMaxDynamicSharedMemorySize, TG_SMEM);
    cudaFuncSetAttribute(flash_kernel, cudaFuncAttributeMaxDynamicSharedMemorySize, FL_SMEM);

    mask_reset_kernel<<<1, 32>>>();
    mask_scan_kernel<<<NTOK/4/256, 256>>>((const unsigned int*)maskraw);
    mask_convert_kernel<<<NTOK/256, 256>>>(maskraw);
    compact_kernel<<<BB, 256>>>();

    wrepack_kernel<<<WT_TOTAL/256, 256>>>(Wq, Wk, Wv, Wo, W1, W2, Wf);
    demo_kernel<<<BB, 256>>>(demo, Wd1, bd1, Wd2, bd2);
    embed_kernel<<<NTOK, 128>>>(values, times, vars, W1t, b1t, W2t, W1v, b1v, W2v, vtab);

    for (int i = 0; i < NLAY; i++) {
        const __nv_bfloat16* l0 = w0p + i*WT_LAYER;
        const __nv_bfloat16* l1 = w1p + i*WT_LAYER;
        const __nv_bfloat16* l2 = w2p + i*WT_LAYER;
        // QKV GEMM with fused K/V plane split (epi=5)
        tgemm_kernel<<<dim3(3, NTOK/128), 256, TG_SMEM>>>(xp, l0 + WT_QKV, l1 + WT_QKV, l2 + WT_QKV,
                                                          nullptr, qkvp, 384, 128, 5);
        flash_kernel<<<dim3(SL/128, BB*HH), 256, FL_SMEM>>>();
        tgemm_kernel<<<dim3(1, NTOK/128), 256, TG_SMEM>>>(op, l0 + WT_WO, l1 + WT_WO, l2 + WT_WO,
                                                          nullptr, xp, 128, 128, 1);
        tgemm_kernel<<<dim3(2, NTOK/128), 256, TG_SMEM>>>(xp, l0 + WT_W1, l1 + WT_W1, l2 + WT_W1,
                                                          b1 + i*DFF, ffp, 256, 128, 2);
        tgemm_kernel<<<dim3(1, NTOK/128), 256, TG_SMEM>>>(ffp, l0 + WT_W2, l1 + WT_W2, l2 + WT_W2,
                                                          b2 + i*DD, xp, 128, 256, 3);
    }

    // fusion attention: tanh(x Wf + bf) via split-GEMM, then dot with uf
    tgemm_kernel<<<dim3(1, NTOK/128), 256, TG_SMEM>>>(xp, w0p + WF_OFF, w1p + WF_OFF, w2p + WF_OFF,
                                                      bf, ffp, 128, 128, 4);
    fuse_reduce_kernel<<<NTOK/8, 256>>>(uf);
    pool_kernel<<<BB, 256>>>();
    head_kernel<<<BB, 256>>>(Wh, bh, out);
}